// round 2
// baseline (speedup 1.0000x reference)
#include <cuda_runtime.h>
#include <cuda_bf16.h>

// Problem constants
#define BMAXR 32768
#define DDIM  1024
#define TTREE 8
#define NODES 63
#define LEAVES 64
#define NPAD  512      // TTREE * 64 (padded node/leaf count)
#define ODIM  128

// Scratch (static device globals -- no runtime allocation)
__device__ float g_s[(size_t)BMAXR * NPAD];    // smooth_step(logits), padded
__device__ float g_Wp[DDIM * NPAD];            // repacked node weights [d][t*64+i]
__device__ float g_LWp[NPAD * ODIM];           // repacked leaf weights [t*64+l][o]

// ---------------------------------------------------------------------------
// Repack kernels (tiny)
// ---------------------------------------------------------------------------
__global__ void repack_w(const float* __restrict__ nw) {
    int idx = blockIdx.x * blockDim.x + threadIdx.x;   // over DDIM*NPAD
    if (idx >= DDIM * NPAD) return;
    int d = idx / NPAD, c = idx % NPAD;
    int t = c >> 6, i = c & 63;
    float v = 0.0f;
    if (i < NODES) v = nw[((size_t)t * DDIM + d) * NODES + i];
    g_Wp[idx] = v;
}

__global__ void repack_lw(const float* __restrict__ lw) {
    int idx = blockIdx.x * blockDim.x + threadIdx.x;   // over NPAD*ODIM
    if (idx >= NPAD * ODIM) return;
    int c = idx / ODIM, o = idx % ODIM;
    int t = c >> 6, l = c & 63;
    g_LWp[idx] = lw[((size_t)t * ODIM + o) * LEAVES + l];
}

// ---------------------------------------------------------------------------
// smooth_step (matches reference: 0 for u<=-0.5, 1 for u>=0.5, else cubic)
// ---------------------------------------------------------------------------
__device__ __forceinline__ float smooth_step(float u) {
    if (u <= -0.5f) return 0.0f;
    if (u >= 0.5f)  return 1.0f;
    return -2.0f * u * u * u + 1.5f * u + 0.5f;
}

// ---------------------------------------------------------------------------
// K1: SGEMM [B x 1024] * [1024 x 512] with smooth_step epilogue -> g_s
// Tile 128x128x8, 256 threads, 8x8 microtile (split 4+4 in both dims)
// ---------------------------------------------------------------------------
#define BM 128
#define BN 128
#define BK 8

__global__ __launch_bounds__(256) void k1_gemm(const float* __restrict__ x) {
    __shared__ float As[BK][BM];
    __shared__ float Bs[BK][BN];

    const int bn = blockIdx.x;   // 0..3
    const int bm = blockIdx.y;   // 0..B/128-1
    const int tid = threadIdx.x;
    const int tx = tid & 15;     // 0..15
    const int ty = tid >> 4;     // 0..15

    const float* xg = x + (size_t)bm * BM * DDIM;
    const float* wg = g_Wp + bn * BN;

    // global load mapping
    const int arow = tid >> 1;          // 0..127
    const int acol = (tid & 1) * 4;     // 0 or 4
    const int brow = tid >> 5;          // 0..7
    const int bcol = (tid & 31) * 4;    // 0..124

    float acc[8][8];
    #pragma unroll
    for (int i = 0; i < 8; i++)
        #pragma unroll
        for (int j = 0; j < 8; j++) acc[i][j] = 0.0f;

    for (int k0 = 0; k0 < DDIM; k0 += BK) {
        float4 av = *(const float4*)(xg + (size_t)arow * DDIM + k0 + acol);
        float4 bv = *(const float4*)(wg + (size_t)(k0 + brow) * NPAD + bcol);
        As[acol + 0][arow] = av.x;
        As[acol + 1][arow] = av.y;
        As[acol + 2][arow] = av.z;
        As[acol + 3][arow] = av.w;
        *(float4*)&Bs[brow][bcol] = bv;
        __syncthreads();

        #pragma unroll
        for (int k = 0; k < BK; ++k) {
            float a[8], b[8];
            #pragma unroll
            for (int i = 0; i < 4; i++) {
                a[i]     = As[k][ty * 4 + i];
                a[4 + i] = As[k][64 + ty * 4 + i];
                b[i]     = Bs[k][tx * 4 + i];
                b[4 + i] = Bs[k][64 + tx * 4 + i];
            }
            #pragma unroll
            for (int i = 0; i < 8; i++)
                #pragma unroll
                for (int j = 0; j < 8; j++)
                    acc[i][j] = fmaf(a[i], b[j], acc[i][j]);
        }
        __syncthreads();
    }

    // epilogue: smooth_step + store to g_s
    #pragma unroll
    for (int hr = 0; hr < 2; hr++) {
        #pragma unroll
        for (int rr = 0; rr < 4; rr++) {
            int i = hr * 4 + rr;
            size_t row = (size_t)bm * BM + hr * 64 + ty * 4 + rr;
            float* srow = g_s + row * NPAD + bn * BN;
            float4 v0, v1;
            v0.x = smooth_step(acc[i][0]); v0.y = smooth_step(acc[i][1]);
            v0.z = smooth_step(acc[i][2]); v0.w = smooth_step(acc[i][3]);
            v1.x = smooth_step(acc[i][4]); v1.y = smooth_step(acc[i][5]);
            v1.z = smooth_step(acc[i][6]); v1.w = smooth_step(acc[i][7]);
            *(float4*)(srow + tx * 4)      = v0;
            *(float4*)(srow + 64 + tx * 4) = v1;
        }
    }
}

// ---------------------------------------------------------------------------
// K2: routing (mu) + leaf GEMM.  32 rows per block, 256 threads.
// Phase A: each thread owns (row, tree), builds 64 leaf probs fully unrolled.
// Phase B: [32 x 128] output tile, K=512, leaf weights streamed via smem.
// ---------------------------------------------------------------------------
#define K2_ROWS 32
#define MU_STRIDE 516   // 512 + pad (mult of 4 for float4, breaks bank aliasing)
#define K2_SMEM_BYTES ((K2_ROWS * MU_STRIDE + K2_ROWS * ODIM) * 4)

__global__ __launch_bounds__(256) void k2_route(float* __restrict__ out) {
    extern __shared__ float sh[];
    float* mu_s = sh;                            // [32][516]
    float* lw_s = sh + K2_ROWS * MU_STRIDE;      // [32][128]

    const int tid = threadIdx.x;
    const size_t bbase = (size_t)blockIdx.x * K2_ROWS;

    // ---------------- Phase A: routing probabilities ----------------
    {
        const int row  = tid & 31;   // lanes spread over rows -> fewer bank conflicts
        const int tree = tid >> 5;   // 0..7
        const float* srow = g_s + (bbase + row) * NPAD + tree * 64;

        float m[64];
        m[0] = 1.0f;
        int start = 0;
        #pragma unroll
        for (int lvl = 0; lvl < 6; ++lvl) {
            const int w = 1 << lvl;
            #pragma unroll
            for (int j = w - 1; j >= 0; --j) {      // descending: in-place safe
                float sv = srow[start + j];
                float p  = m[j];
                m[2 * j]     = p * sv;
                m[2 * j + 1] = p * (1.0f - sv);
            }
            start += w;
        }
        float* mrow = mu_s + row * MU_STRIDE + tree * 64;
        #pragma unroll
        for (int l = 0; l < 64; ++l) mrow[l] = m[l];
    }
    __syncthreads();

    // ---------------- Phase B: out[32][128] = mu[32][512] * LW[512][128] ----
    const int tx = tid & 31;     // col group: cols tx*4..+3
    const int ty = tid >> 5;     // row group: rows ty*4..+3

    float acc[4][4];
    #pragma unroll
    for (int r = 0; r < 4; r++)
        #pragma unroll
        for (int c = 0; c < 4; c++) acc[r][c] = 0.0f;

    for (int kk = 0; kk < NPAD; kk += 32) {
        // load LW chunk [32][128] cooperatively (coalesced float4)
        const float4* src = (const float4*)(g_LWp + (size_t)kk * ODIM);
        float4* dst = (float4*)lw_s;
        #pragma unroll
        for (int q = 0; q < 4; q++) dst[tid + 256 * q] = src[tid + 256 * q];
        __syncthreads();

        #pragma unroll 8
        for (int k = 0; k < 32; ++k) {
            float4 bv = *(const float4*)&lw_s[k * ODIM + tx * 4];
            #pragma unroll
            for (int r = 0; r < 4; r++) {
                float a = mu_s[(ty * 4 + r) * MU_STRIDE + kk + k];  // broadcast
                acc[r][0] = fmaf(a, bv.x, acc[r][0]);
                acc[r][1] = fmaf(a, bv.y, acc[r][1]);
                acc[r][2] = fmaf(a, bv.z, acc[r][2]);
                acc[r][3] = fmaf(a, bv.w, acc[r][3]);
            }
        }
        __syncthreads();
    }

    // store
    #pragma unroll
    for (int r = 0; r < 4; r++) {
        float4 v = make_float4(acc[r][0], acc[r][1], acc[r][2], acc[r][3]);
        *(float4*)(out + (bbase + ty * 4 + r) * ODIM + tx * 4) = v;
    }
}

// ---------------------------------------------------------------------------
// Launch
// ---------------------------------------------------------------------------
extern "C" void kernel_launch(void* const* d_in, const int* in_sizes, int n_in,
                              void* d_out, int out_size) {
    const float* x  = (const float*)d_in[0];   // [B, 1024]
    const float* nw = (const float*)d_in[1];   // [8, 1024, 63]
    const float* lw = (const float*)d_in[2];   // [8, 128, 64]
    float* out = (float*)d_out;                // [B, 128]

    int Brows = in_sizes[0] / DDIM;            // 32768

    cudaFuncSetAttribute(k2_route, cudaFuncAttributeMaxDynamicSharedMemorySize,
                         K2_SMEM_BYTES);

    repack_w <<< (DDIM * NPAD + 255) / 256, 256 >>> (nw);
    repack_lw<<< (NPAD * ODIM + 255) / 256, 256 >>> (lw);
    k1_gemm  <<< dim3(NPAD / BN, Brows / BM), 256 >>> (x);
    k2_route <<< Brows / K2_ROWS, 256, K2_SMEM_BYTES >>> (out);
}

// round 4
// speedup vs baseline: 1.8365x; 1.8365x over previous
#include <cuda_runtime.h>
#include <cuda_bf16.h>
#include <cstdint>

// Problem constants
#define BMAXR 32768
#define DDIM  1024
#define TTREE 8
#define NODES 63
#define LEAVES 64
#define NPAD  512
#define ODIM  128
#define KEFF  3072     // 3 * DDIM (hi*hi, hi*lo, lo*hi)

// Scratch (static device globals -- no runtime allocation)
__device__ __align__(256) float          g_s[(size_t)BMAXR * NPAD];
__device__ __align__(256) __nv_bfloat16  g_xhi[(size_t)BMAXR * DDIM];
__device__ __align__(256) __nv_bfloat16  g_xlo[(size_t)BMAXR * DDIM];
__device__ __align__(256) __nv_bfloat16  g_Bt[(size_t)NPAD * KEFF];  // [n][k3]
__device__ __align__(256) float          g_LWp[NPAD * ODIM];

// ===========================================================================
// PTX helpers (all arch-generic: sm_80+ / sm_75+)
// ===========================================================================
__device__ __forceinline__ uint32_t smem_u32(const void* p) {
    uint32_t a;
    asm("{ .reg .u64 t; cvta.to.shared.u64 t, %1; cvt.u32.u64 %0, t; }"
        : "=r"(a) : "l"(p));
    return a;
}
__device__ __forceinline__ void cp16(uint32_t dst, const void* src) {
    asm volatile("cp.async.cg.shared.global [%0], [%1], 16;"
                 :: "r"(dst), "l"(src) : "memory");
}
#define CP_COMMIT() asm volatile("cp.async.commit_group;" ::: "memory")
#define CP_WAIT(n)  asm volatile("cp.async.wait_group %0;" :: "n"(n) : "memory")

__device__ __forceinline__ void ldsm4(uint32_t& r0, uint32_t& r1,
                                      uint32_t& r2, uint32_t& r3, uint32_t addr) {
    asm volatile("ldmatrix.sync.aligned.m8n8.x4.shared.b16 {%0,%1,%2,%3}, [%4];"
                 : "=r"(r0), "=r"(r1), "=r"(r2), "=r"(r3) : "r"(addr));
}
__device__ __forceinline__ void mma16816(float* d, const uint32_t* a,
                                         const uint32_t* b) {
    asm volatile("mma.sync.aligned.m16n8k16.row.col.f32.bf16.bf16.f32 "
                 "{%0,%1,%2,%3},{%4,%5,%6,%7},{%8,%9},{%0,%1,%2,%3};"
                 : "+f"(d[0]), "+f"(d[1]), "+f"(d[2]), "+f"(d[3])
                 : "r"(a[0]), "r"(a[1]), "r"(a[2]), "r"(a[3]),
                   "r"(b[0]), "r"(b[1]));
}

__device__ __forceinline__ float smooth_step(float u) {
    if (u <= -0.5f) return 0.0f;
    if (u >= 0.5f)  return 1.0f;
    return -2.0f * u * u * u + 1.5f * u + 0.5f;
}

// ===========================================================================
// Pre-pass kernels
// ===========================================================================
__global__ void convert_x(const float* __restrict__ x) {
    int i = blockIdx.x * blockDim.x + threadIdx.x;     // over n/4 float4
    float4 v = ((const float4*)x)[i];
    __nv_bfloat16 h[4], l[4];
    float f[4] = {v.x, v.y, v.z, v.w};
    #pragma unroll
    for (int j = 0; j < 4; j++) {
        h[j] = __float2bfloat16(f[j]);
        l[j] = __float2bfloat16(f[j] - __bfloat162float(h[j]));
    }
    *(uint64_t*)&g_xhi[(size_t)i * 4] = *(uint64_t*)h;
    *(uint64_t*)&g_xlo[(size_t)i * 4] = *(uint64_t*)l;
}

__global__ void repack_b(const float* __restrict__ nw) {
    int idx = blockIdx.x * blockDim.x + threadIdx.x;   // over NPAD*KEFF
    if (idx >= NPAD * KEFF) return;
    int n = idx / KEFF, k3 = idx % KEFF;
    int t = n >> 6, i = n & 63;
    int part = k3 >> 10, k = k3 & 1023;
    float w = 0.0f;
    if (i < NODES) w = nw[((size_t)t * DDIM + k) * NODES + i];
    __nv_bfloat16 hi = __float2bfloat16(w);
    __nv_bfloat16 outv = (part == 1) ? __float2bfloat16(w - __bfloat162float(hi)) : hi;
    g_Bt[idx] = outv;
}

__global__ void repack_lw(const float* __restrict__ lw) {
    int idx = blockIdx.x * blockDim.x + threadIdx.x;   // over NPAD*ODIM
    if (idx >= NPAD * ODIM) return;
    int c = idx / ODIM, o = idx % ODIM;
    int t = c >> 6, l = c & 63;
    g_LWp[idx] = lw[((size_t)t * ODIM + o) * LEAVES + l];
}

// ===========================================================================
// K1: bf16 mma.sync GEMM  C[B x 512] = A[B x 3072] * Bt[512 x 3072]^T
// CTA tile 128x128, 8 warps x (64x32), K chunk 64, 3-stage cp.async.
// Fused smooth_step epilogue -> g_s.
// ===========================================================================
#define A_ST 72                          // halves per smem row (64 + 8 pad)
#define A_BYTES (128 * A_ST * 2)         // 18432 per tile
#define STAGE_BYTES (2 * A_BYTES)        // A + B = 36864
#define K1_STAGES 3
#define NCHUNK 48
#define K1_SMEM (K1_STAGES * STAGE_BYTES)   // 110592

__global__ __launch_bounds__(256, 2) void k1_tc() {
    extern __shared__ char smraw[];
    const uint32_t smb = smem_u32(smraw);

    const int tid  = threadIdx.x;
    const int lane = tid & 31;
    const int wid  = tid >> 5;
    const int bm   = blockIdx.x;          // 0..255
    const int bn   = blockIdx.y;          // 0..3
    const int wm   = (wid & 1) * 64;      // warp M base within tile
    const int wn   = (wid >> 1) * 32;     // warp N base within tile

    // per-thread load coords (4 x 16B per operand per stage)
    // unit u: row = u>>3, seg = u&7  (8 x 16B = 128B per row)
    // stage loader
    auto load_stage = [&](int c) {
        const int slot = c % K1_STAGES;
        const uint32_t sa = smb + slot * STAGE_BYTES;
        const uint32_t sb = sa + A_BYTES;
        const int part = c >> 4;                        // 0,1: hi  2: lo
        const __nv_bfloat16* ap = (part == 2) ? g_xlo : g_xhi;
        const __nv_bfloat16* abase = ap + (size_t)bm * 128 * DDIM + (c & 15) * 64;
        const __nv_bfloat16* bbase = g_Bt + (size_t)bn * 128 * KEFF + (size_t)c * 64;
        #pragma unroll
        for (int i = 0; i < 4; i++) {
            int u = tid + 256 * i;
            int row = u >> 3, seg = u & 7;
            cp16(sa + (uint32_t)(row * A_ST + seg * 8) * 2,
                 abase + (size_t)row * DDIM + seg * 8);
        }
        #pragma unroll
        for (int i = 0; i < 4; i++) {
            int u = tid + 256 * i;
            int row = u >> 3, seg = u & 7;
            cp16(sb + (uint32_t)(row * A_ST + seg * 8) * 2,
                 bbase + (size_t)row * KEFF + seg * 8);
        }
        CP_COMMIT();
    };

    float acc[4][4][4];
    #pragma unroll
    for (int t = 0; t < 4; t++)
        #pragma unroll
        for (int g = 0; g < 4; g++)
            #pragma unroll
            for (int e = 0; e < 4; e++) acc[t][g][e] = 0.0f;

    load_stage(0);
    load_stage(1);

    // precomputed lane-dependent ldmatrix offsets (halves)
    const int a_m   = (lane & 15);
    const int a_k8  = (lane >> 4) * 8;
    const int b_n   = ((lane >> 4) << 3) + (lane & 7);
    const int b_k8  = ((lane >> 3) & 1) * 8;

    for (int c = 0; c < NCHUNK; ++c) {
        if (c + 2 < NCHUNK) { load_stage(c + 2); CP_WAIT(2); }
        else if (c == NCHUNK - 2) { CP_WAIT(1); }
        else { CP_WAIT(0); }
        __syncthreads();

        const int slot = c % K1_STAGES;
        const uint32_t sa = smb + slot * STAGE_BYTES;
        const uint32_t sb = sa + A_BYTES;

        #pragma unroll
        for (int kk = 0; kk < 4; kk++) {
            uint32_t af[4][4];
            #pragma unroll
            for (int t = 0; t < 4; t++) {
                int m = wm + t * 16 + a_m;
                ldsm4(af[t][0], af[t][1], af[t][2], af[t][3],
                      sa + (uint32_t)(m * A_ST + kk * 16 + a_k8) * 2);
            }
            uint32_t bf[2][4];
            #pragma unroll
            for (int g16 = 0; g16 < 2; g16++) {
                int n = wn + g16 * 16 + b_n;
                ldsm4(bf[g16][0], bf[g16][1], bf[g16][2], bf[g16][3],
                      sb + (uint32_t)(n * A_ST + kk * 16 + b_k8) * 2);
            }
            #pragma unroll
            for (int t = 0; t < 4; t++)
                #pragma unroll
                for (int g = 0; g < 4; g++)
                    mma16816(acc[t][g], af[t], &bf[g >> 1][(g & 1) * 2]);
        }
        __syncthreads();   // protect slot before reuse by load(c+3)
    }

    // ---- epilogue: smooth_step, stage C in smem, coalesced store ----
    float* cs = (float*)smraw;          // [128][132]
    const int r0 = lane >> 2;
    const int c0 = (lane & 3) * 2;
    #pragma unroll
    for (int t = 0; t < 4; t++) {
        #pragma unroll
        for (int g = 0; g < 4; g++) {
            int m = wm + t * 16 + r0;
            int n = wn + g * 8 + c0;
            cs[m * 132 + n]           = smooth_step(acc[t][g][0]);
            cs[m * 132 + n + 1]       = smooth_step(acc[t][g][1]);
            cs[(m + 8) * 132 + n]     = smooth_step(acc[t][g][2]);
            cs[(m + 8) * 132 + n + 1] = smooth_step(acc[t][g][3]);
        }
    }
    __syncthreads();

    {
        const int row  = tid >> 1;
        const int half = tid & 1;
        float4* dst = (float4*)(g_s + ((size_t)bm * 128 + row) * NPAD
                                + bn * 128 + half * 64);
        const float* srcr = cs + row * 132 + half * 64;
        #pragma unroll
        for (int j = 0; j < 16; j++)
            dst[j] = *(const float4*)(srcr + j * 4);
    }
}

// ===========================================================================
// K2: routing (mu) + leaf GEMM.
// s tile staged TRANSPOSED in smem ([col][row], stride 33) -> conflict-free
// routing; mu overwrites in place; Phase B dense FMA.
// ===========================================================================
#define K2_ROWS 32
#define ST 33
#define K2_SMEM ((512 * ST + K2_ROWS * ODIM) * 4)   // 67584 + 16384 = 83968

__global__ __launch_bounds__(256) void k2_route(float* __restrict__ out) {
    extern __shared__ float sh[];
    float* st_s = sh;                 // [512][33] transposed s / mu
    float* lw_s = sh + 512 * ST;      // [32][128]

    const int tid = threadIdx.x;
    const size_t bbase = (size_t)blockIdx.x * K2_ROWS;

    // ---- stage s tile (coalesced read, transposed store) ----
    {
        const float4* xsrc = (const float4*)(g_s + bbase * NPAD);
        #pragma unroll
        for (int i = 0; i < 16; i++) {
            int u = tid + 256 * i;           // 0..4095
            int row = u >> 7, c4 = u & 127;
            float4 v = xsrc[row * 128 + c4];
            st_s[(c4 * 4 + 0) * ST + row] = v.x;
            st_s[(c4 * 4 + 1) * ST + row] = v.y;
            st_s[(c4 * 4 + 2) * ST + row] = v.z;
            st_s[(c4 * 4 + 3) * ST + row] = v.w;
        }
    }
    __syncthreads();

    // ---- Phase A: routing probabilities (conflict-free LDS/STS) ----
    {
        const int row  = tid & 31;
        const int tree = tid >> 5;
        const float* sc = st_s + (size_t)tree * 64 * ST + row;

        float m[64];
        m[0] = 1.0f;
        int start = 0;
        #pragma unroll
        for (int lvl = 0; lvl < 6; ++lvl) {
            const int w = 1 << lvl;
            #pragma unroll
            for (int j = w - 1; j >= 0; --j) {
                float sv = sc[(start + j) * ST];
                float p  = m[j];
                m[2 * j]     = p * sv;
                m[2 * j + 1] = p * (1.0f - sv);
            }
            start += w;
        }
        float* mc = st_s + (size_t)tree * 64 * ST + row;
        #pragma unroll
        for (int l = 0; l < 64; ++l) mc[l * ST] = m[l];
    }
    __syncthreads();

    // ---- Phase B: out[32][128] = mu[32][512] * LW[512][128] ----
    const int tx = tid & 31;
    const int ty = tid >> 5;

    float acc[4][4];
    #pragma unroll
    for (int r = 0; r < 4; r++)
        #pragma unroll
        for (int c = 0; c < 4; c++) acc[r][c] = 0.0f;

    for (int kk = 0; kk < NPAD; kk += 32) {
        const float4* src = (const float4*)(g_LWp + (size_t)kk * ODIM);
        float4* dst = (float4*)lw_s;
        #pragma unroll
        for (int q = 0; q < 4; q++) dst[tid + 256 * q] = src[tid + 256 * q];
        __syncthreads();

        #pragma unroll 8
        for (int k = 0; k < 32; ++k) {
            float4 bv = *(const float4*)&lw_s[k * ODIM + tx * 4];
            #pragma unroll
            for (int r = 0; r < 4; r++) {
                float a = st_s[(kk + k) * ST + ty * 4 + r];   // warp broadcast
                acc[r][0] = fmaf(a, bv.x, acc[r][0]);
                acc[r][1] = fmaf(a, bv.y, acc[r][1]);
                acc[r][2] = fmaf(a, bv.z, acc[r][2]);
                acc[r][3] = fmaf(a, bv.w, acc[r][3]);
            }
        }
        __syncthreads();
    }

    #pragma unroll
    for (int r = 0; r < 4; r++) {
        float4 v = make_float4(acc[r][0], acc[r][1], acc[r][2], acc[r][3]);
        *(float4*)(out + (bbase + ty * 4 + r) * ODIM + tx * 4) = v;
    }
}

// ===========================================================================
// Launch
// ===========================================================================
extern "C" void kernel_launch(void* const* d_in, const int* in_sizes, int n_in,
                              void* d_out, int out_size) {
    const float* x  = (const float*)d_in[0];   // [B, 1024]
    const float* nw = (const float*)d_in[1];   // [8, 1024, 63]
    const float* lw = (const float*)d_in[2];   // [8, 128, 64]
    float* out = (float*)d_out;                // [B, 128]

    int Brows = in_sizes[0] / DDIM;            // 32768

    cudaFuncSetAttribute(k1_tc, cudaFuncAttributeMaxDynamicSharedMemorySize, K1_SMEM);
    cudaFuncSetAttribute(k2_route, cudaFuncAttributeMaxDynamicSharedMemorySize, K2_SMEM);

    convert_x<<< (Brows * DDIM / 4 + 255) / 256, 256 >>>(x);
    repack_b <<< (NPAD * KEFF + 255) / 256, 256 >>>(nw);
    repack_lw<<< (NPAD * ODIM + 255) / 256, 256 >>>(lw);
    k1_tc    <<< dim3(Brows / 128, NPAD / 128), 256, K1_SMEM >>>();
    k2_route <<< Brows / K2_ROWS, 256, K2_SMEM >>>(out);
}

// round 5
// speedup vs baseline: 2.1742x; 1.1839x over previous
#include <cuda_runtime.h>
#include <cuda_bf16.h>
#include <cstdint>

// Problem constants
#define BMAXR 32768
#define DDIM  1024
#define TTREE 8
#define NODES 63
#define LEAVES 64
#define NPAD  512
#define ODIM  128
#define KEFF  3072     // 3 * DDIM (hi*hi, hi*lo, lo*hi)
#define KEFF2 1536     // 3 * NPAD for leaf GEMM

// Scratch (static device globals -- no runtime allocation)
__device__ __align__(256) float          g_s[(size_t)BMAXR * NPAD];
__device__ __align__(256) __nv_bfloat16  g_xhi[(size_t)BMAXR * DDIM];
__device__ __align__(256) __nv_bfloat16  g_xlo[(size_t)BMAXR * DDIM];
__device__ __align__(256) __nv_bfloat16  g_Bt[(size_t)NPAD * KEFF];   // [n][k3]
__device__ __align__(256) __nv_bfloat16  g_muh[(size_t)BMAXR * NPAD];
__device__ __align__(256) __nv_bfloat16  g_mul[(size_t)BMAXR * NPAD];
__device__ __align__(256) __nv_bfloat16  g_LB[(size_t)ODIM * KEFF2];  // [o][k3]

// ===========================================================================
// PTX helpers (all arch-generic: sm_80+ / sm_75+)
// ===========================================================================
__device__ __forceinline__ uint32_t smem_u32(const void* p) {
    uint32_t a;
    asm("{ .reg .u64 t; cvta.to.shared.u64 t, %1; cvt.u32.u64 %0, t; }"
        : "=r"(a) : "l"(p));
    return a;
}
__device__ __forceinline__ void cp16(uint32_t dst, const void* src) {
    asm volatile("cp.async.cg.shared.global [%0], [%1], 16;"
                 :: "r"(dst), "l"(src) : "memory");
}
#define CP_COMMIT() asm volatile("cp.async.commit_group;" ::: "memory")
#define CP_WAIT(n)  asm volatile("cp.async.wait_group %0;" :: "n"(n) : "memory")

__device__ __forceinline__ void ldsm4(uint32_t& r0, uint32_t& r1,
                                      uint32_t& r2, uint32_t& r3, uint32_t addr) {
    asm volatile("ldmatrix.sync.aligned.m8n8.x4.shared.b16 {%0,%1,%2,%3}, [%4];"
                 : "=r"(r0), "=r"(r1), "=r"(r2), "=r"(r3) : "r"(addr));
}
__device__ __forceinline__ void mma16816(float* d, const uint32_t* a,
                                         const uint32_t* b) {
    asm volatile("mma.sync.aligned.m16n8k16.row.col.f32.bf16.bf16.f32 "
                 "{%0,%1,%2,%3},{%4,%5,%6,%7},{%8,%9},{%0,%1,%2,%3};"
                 : "+f"(d[0]), "+f"(d[1]), "+f"(d[2]), "+f"(d[3])
                 : "r"(a[0]), "r"(a[1]), "r"(a[2]), "r"(a[3]),
                   "r"(b[0]), "r"(b[1]));
}

__device__ __forceinline__ float smooth_step(float u) {
    if (u <= -0.5f) return 0.0f;
    if (u >= 0.5f)  return 1.0f;
    return -2.0f * u * u * u + 1.5f * u + 0.5f;
}

// ===========================================================================
// Pre-pass kernels
// ===========================================================================
__global__ void convert_x(const float* __restrict__ x) {
    int i = blockIdx.x * blockDim.x + threadIdx.x;     // over n/4 float4
    float4 v = ((const float4*)x)[i];
    __nv_bfloat16 h[4], l[4];
    float f[4] = {v.x, v.y, v.z, v.w};
    #pragma unroll
    for (int j = 0; j < 4; j++) {
        h[j] = __float2bfloat16(f[j]);
        l[j] = __float2bfloat16(f[j] - __bfloat162float(h[j]));
    }
    *(uint64_t*)&g_xhi[(size_t)i * 4] = *(uint64_t*)h;
    *(uint64_t*)&g_xlo[(size_t)i * 4] = *(uint64_t*)l;
}

__global__ void repack_b(const float* __restrict__ nw) {
    int idx = blockIdx.x * blockDim.x + threadIdx.x;   // over NPAD*KEFF
    if (idx >= NPAD * KEFF) return;
    int n = idx / KEFF, k3 = idx % KEFF;
    int t = n >> 6, i = n & 63;
    int part = k3 >> 10, k = k3 & 1023;
    float w = 0.0f;
    if (i < NODES) w = nw[((size_t)t * DDIM + k) * NODES + i];
    __nv_bfloat16 hi = __float2bfloat16(w);
    __nv_bfloat16 outv = (part == 1) ? __float2bfloat16(w - __bfloat162float(hi)) : hi;
    g_Bt[idx] = outv;
}

// leaf weights -> [o][k3] bf16, k3 = part*512 + t*64 + l; parts: hi, hi, lo
__global__ void repack_lb(const float* __restrict__ lw) {
    int idx = blockIdx.x * blockDim.x + threadIdx.x;   // over ODIM*KEFF2
    if (idx >= ODIM * KEFF2) return;
    int o = idx / KEFF2, k3 = idx % KEFF2;
    int part = k3 >> 9, k = k3 & 511;
    int t = k >> 6, l = k & 63;
    float w = lw[((size_t)t * ODIM + o) * LEAVES + l];
    __nv_bfloat16 hi = __float2bfloat16(w);
    __nv_bfloat16 outv = (part == 2) ? __float2bfloat16(w - __bfloat162float(hi)) : hi;
    g_LB[idx] = outv;
}

// ===========================================================================
// K1: bf16 mma.sync GEMM  C[B x 512] = A[B x 3072] * Bt[512 x 3072]^T
// CTA tile 128x128, 8 warps x (64x32), K chunk 64, 3-stage cp.async.
// Fused smooth_step epilogue -> g_s.   (UNCHANGED from passing round)
// ===========================================================================
#define A_ST 72
#define A_BYTES (128 * A_ST * 2)
#define STAGE_BYTES (2 * A_BYTES)
#define K1_STAGES 3
#define NCHUNK 48
#define K1_SMEM (K1_STAGES * STAGE_BYTES)

__global__ __launch_bounds__(256, 2) void k1_tc() {
    extern __shared__ char smraw[];
    const uint32_t smb = smem_u32(smraw);

    const int tid  = threadIdx.x;
    const int lane = tid & 31;
    const int wid  = tid >> 5;
    const int bm   = blockIdx.x;
    const int bn   = blockIdx.y;
    const int wm   = (wid & 1) * 64;
    const int wn   = (wid >> 1) * 32;

    auto load_stage = [&](int c) {
        const int slot = c % K1_STAGES;
        const uint32_t sa = smb + slot * STAGE_BYTES;
        const uint32_t sb = sa + A_BYTES;
        const int part = c >> 4;
        const __nv_bfloat16* ap = (part == 2) ? g_xlo : g_xhi;
        const __nv_bfloat16* abase = ap + (size_t)bm * 128 * DDIM + (c & 15) * 64;
        const __nv_bfloat16* bbase = g_Bt + (size_t)bn * 128 * KEFF + (size_t)c * 64;
        #pragma unroll
        for (int i = 0; i < 4; i++) {
            int u = tid + 256 * i;
            int row = u >> 3, seg = u & 7;
            cp16(sa + (uint32_t)(row * A_ST + seg * 8) * 2,
                 abase + (size_t)row * DDIM + seg * 8);
        }
        #pragma unroll
        for (int i = 0; i < 4; i++) {
            int u = tid + 256 * i;
            int row = u >> 3, seg = u & 7;
            cp16(sb + (uint32_t)(row * A_ST + seg * 8) * 2,
                 bbase + (size_t)row * KEFF + seg * 8);
        }
        CP_COMMIT();
    };

    float acc[4][4][4];
    #pragma unroll
    for (int t = 0; t < 4; t++)
        #pragma unroll
        for (int g = 0; g < 4; g++)
            #pragma unroll
            for (int e = 0; e < 4; e++) acc[t][g][e] = 0.0f;

    load_stage(0);
    load_stage(1);

    const int a_m   = (lane & 15);
    const int a_k8  = (lane >> 4) * 8;
    const int b_n   = ((lane >> 4) << 3) + (lane & 7);
    const int b_k8  = ((lane >> 3) & 1) * 8;

    for (int c = 0; c < NCHUNK; ++c) {
        if (c + 2 < NCHUNK) { load_stage(c + 2); CP_WAIT(2); }
        else if (c == NCHUNK - 2) { CP_WAIT(1); }
        else { CP_WAIT(0); }
        __syncthreads();

        const int slot = c % K1_STAGES;
        const uint32_t sa = smb + slot * STAGE_BYTES;
        const uint32_t sb = sa + A_BYTES;

        #pragma unroll
        for (int kk = 0; kk < 4; kk++) {
            uint32_t af[4][4];
            #pragma unroll
            for (int t = 0; t < 4; t++) {
                int m = wm + t * 16 + a_m;
                ldsm4(af[t][0], af[t][1], af[t][2], af[t][3],
                      sa + (uint32_t)(m * A_ST + kk * 16 + a_k8) * 2);
            }
            uint32_t bf[2][4];
            #pragma unroll
            for (int g16 = 0; g16 < 2; g16++) {
                int n = wn + g16 * 16 + b_n;
                ldsm4(bf[g16][0], bf[g16][1], bf[g16][2], bf[g16][3],
                      sb + (uint32_t)(n * A_ST + kk * 16 + b_k8) * 2);
            }
            #pragma unroll
            for (int t = 0; t < 4; t++)
                #pragma unroll
                for (int g = 0; g < 4; g++)
                    mma16816(acc[t][g], af[t], &bf[g >> 1][(g & 1) * 2]);
        }
        __syncthreads();
    }

    float* cs = (float*)smraw;          // [128][132]
    const int r0 = lane >> 2;
    const int c0 = (lane & 3) * 2;
    #pragma unroll
    for (int t = 0; t < 4; t++) {
        #pragma unroll
        for (int g = 0; g < 4; g++) {
            int m = wm + t * 16 + r0;
            int n = wn + g * 8 + c0;
            cs[m * 132 + n]           = smooth_step(acc[t][g][0]);
            cs[m * 132 + n + 1]       = smooth_step(acc[t][g][1]);
            cs[(m + 8) * 132 + n]     = smooth_step(acc[t][g][2]);
            cs[(m + 8) * 132 + n + 1] = smooth_step(acc[t][g][3]);
        }
    }
    __syncthreads();

    {
        const int row  = tid >> 1;
        const int half = tid & 1;
        float4* dst = (float4*)(g_s + ((size_t)bm * 128 + row) * NPAD
                                + bn * 128 + half * 64);
        const float* srcr = cs + row * 132 + half * 64;
        #pragma unroll
        for (int j = 0; j < 16; j++)
            dst[j] = *(const float4*)(srcr + j * 4);
    }
}

// ===========================================================================
// K2a: routing only.  Stage s transposed in smem, route in regs, write mu
// as bf16 hi/lo split (contiguous 128B per thread).
// ===========================================================================
#define K2_ROWS 32
#define ST 33
#define K2_SMEM (512 * ST * 4)    // 67584

__global__ __launch_bounds__(256) void k2_route() {
    extern __shared__ float st_s[];   // [512][33] transposed s

    const int tid = threadIdx.x;
    const size_t bbase = (size_t)blockIdx.x * K2_ROWS;

    // ---- stage s tile (coalesced read, transposed store) ----
    {
        const float4* xsrc = (const float4*)(g_s + bbase * NPAD);
        #pragma unroll
        for (int i = 0; i < 16; i++) {
            int u = tid + 256 * i;           // 0..4095
            int row = u >> 7, c4 = u & 127;
            float4 v = xsrc[row * 128 + c4];
            st_s[(c4 * 4 + 0) * ST + row] = v.x;
            st_s[(c4 * 4 + 1) * ST + row] = v.y;
            st_s[(c4 * 4 + 2) * ST + row] = v.z;
            st_s[(c4 * 4 + 3) * ST + row] = v.w;
        }
    }
    __syncthreads();

    // ---- route + split + store ----
    {
        const int row  = tid & 31;
        const int tree = tid >> 5;
        const float* sc = st_s + (size_t)tree * 64 * ST + row;

        float m[64];
        m[0] = 1.0f;
        int start = 0;
        #pragma unroll
        for (int lvl = 0; lvl < 6; ++lvl) {
            const int w = 1 << lvl;
            #pragma unroll
            for (int j = w - 1; j >= 0; --j) {
                float sv = sc[(start + j) * ST];
                float p  = m[j];
                m[2 * j]     = p * sv;
                m[2 * j + 1] = p * (1.0f - sv);
            }
            start += w;
        }

        const size_t obase = (bbase + row) * NPAD + tree * 64;
        #pragma unroll
        for (int g = 0; g < 8; ++g) {
            __nv_bfloat16 hb[8], lb[8];
            #pragma unroll
            for (int i = 0; i < 8; ++i) {
                float v = m[g * 8 + i];
                hb[i] = __float2bfloat16(v);
                lb[i] = __float2bfloat16(v - __bfloat162float(hb[i]));
            }
            *(uint4*)(g_muh + obase + g * 8) = *(uint4*)hb;
            *(uint4*)(g_mul + obase + g * 8) = *(uint4*)lb;
        }
    }
}

// ===========================================================================
// K3: leaf GEMM on tensor cores.
// out[B x 128] = [muh | mul | muh][B x 1536] * g_LB[128 x 1536]^T
// Same pipeline as K1, NCHUNK=24, single N tile, plain store epilogue.
// ===========================================================================
#define NCHUNK3 24

__global__ __launch_bounds__(256, 2) void k3_leaf(float* __restrict__ out) {
    extern __shared__ char smraw[];
    const uint32_t smb = smem_u32(smraw);

    const int tid  = threadIdx.x;
    const int lane = tid & 31;
    const int wid  = tid >> 5;
    const int bm   = blockIdx.x;
    const int wm   = (wid & 1) * 64;
    const int wn   = (wid >> 1) * 32;

    auto load_stage = [&](int c) {
        const int slot = c % K1_STAGES;
        const uint32_t sa = smb + slot * STAGE_BYTES;
        const uint32_t sb = sa + A_BYTES;
        const int part = c >> 3;                       // 0:muh 1:mul 2:muh
        const __nv_bfloat16* ap = (part == 1) ? g_mul : g_muh;
        const __nv_bfloat16* abase = ap + (size_t)bm * 128 * NPAD + (c & 7) * 64;
        const __nv_bfloat16* bbase = g_LB + (size_t)c * 64;
        #pragma unroll
        for (int i = 0; i < 4; i++) {
            int u = tid + 256 * i;
            int row = u >> 3, seg = u & 7;
            cp16(sa + (uint32_t)(row * A_ST + seg * 8) * 2,
                 abase + (size_t)row * NPAD + seg * 8);
        }
        #pragma unroll
        for (int i = 0; i < 4; i++) {
            int u = tid + 256 * i;
            int row = u >> 3, seg = u & 7;
            cp16(sb + (uint32_t)(row * A_ST + seg * 8) * 2,
                 bbase + (size_t)row * KEFF2 + seg * 8);
        }
        CP_COMMIT();
    };

    float acc[4][4][4];
    #pragma unroll
    for (int t = 0; t < 4; t++)
        #pragma unroll
        for (int g = 0; g < 4; g++)
            #pragma unroll
            for (int e = 0; e < 4; e++) acc[t][g][e] = 0.0f;

    load_stage(0);
    load_stage(1);

    const int a_m   = (lane & 15);
    const int a_k8  = (lane >> 4) * 8;
    const int b_n   = ((lane >> 4) << 3) + (lane & 7);
    const int b_k8  = ((lane >> 3) & 1) * 8;

    for (int c = 0; c < NCHUNK3; ++c) {
        if (c + 2 < NCHUNK3) { load_stage(c + 2); CP_WAIT(2); }
        else if (c == NCHUNK3 - 2) { CP_WAIT(1); }
        else { CP_WAIT(0); }
        __syncthreads();

        const int slot = c % K1_STAGES;
        const uint32_t sa = smb + slot * STAGE_BYTES;
        const uint32_t sb = sa + A_BYTES;

        #pragma unroll
        for (int kk = 0; kk < 4; kk++) {
            uint32_t af[4][4];
            #pragma unroll
            for (int t = 0; t < 4; t++) {
                int m = wm + t * 16 + a_m;
                ldsm4(af[t][0], af[t][1], af[t][2], af[t][3],
                      sa + (uint32_t)(m * A_ST + kk * 16 + a_k8) * 2);
            }
            uint32_t bf[2][4];
            #pragma unroll
            for (int g16 = 0; g16 < 2; g16++) {
                int n = wn + g16 * 16 + b_n;
                ldsm4(bf[g16][0], bf[g16][1], bf[g16][2], bf[g16][3],
                      sb + (uint32_t)(n * A_ST + kk * 16 + b_k8) * 2);
            }
            #pragma unroll
            for (int t = 0; t < 4; t++)
                #pragma unroll
                for (int g = 0; g < 4; g++)
                    mma16816(acc[t][g], af[t], &bf[g >> 1][(g & 1) * 2]);
        }
        __syncthreads();
    }

    // epilogue: stage in smem, coalesced store to out
    float* cs = (float*)smraw;          // [128][132]
    const int r0 = lane >> 2;
    const int c0 = (lane & 3) * 2;
    #pragma unroll
    for (int t = 0; t < 4; t++) {
        #pragma unroll
        for (int g = 0; g < 4; g++) {
            int m = wm + t * 16 + r0;
            int n = wn + g * 8 + c0;
            cs[m * 132 + n]           = acc[t][g][0];
            cs[m * 132 + n + 1]       = acc[t][g][1];
            cs[(m + 8) * 132 + n]     = acc[t][g][2];
            cs[(m + 8) * 132 + n + 1] = acc[t][g][3];
        }
    }
    __syncthreads();

    {
        const int row  = tid >> 1;
        const int half = tid & 1;
        float4* dst = (float4*)(out + ((size_t)bm * 128 + row) * ODIM + half * 64);
        const float* srcr = cs + row * 132 + half * 64;
        #pragma unroll
        for (int j = 0; j < 16; j++)
            dst[j] = *(const float4*)(srcr + j * 4);
    }
}

// ===========================================================================
// Launch
// ===========================================================================
extern "C" void kernel_launch(void* const* d_in, const int* in_sizes, int n_in,
                              void* d_out, int out_size) {
    const float* x  = (const float*)d_in[0];   // [B, 1024]
    const float* nw = (const float*)d_in[1];   // [8, 1024, 63]
    const float* lw = (const float*)d_in[2];   // [8, 128, 64]
    float* out = (float*)d_out;                // [B, 128]

    int Brows = in_sizes[0] / DDIM;            // 32768

    cudaFuncSetAttribute(k1_tc,   cudaFuncAttributeMaxDynamicSharedMemorySize, K1_SMEM);
    cudaFuncSetAttribute(k2_route,cudaFuncAttributeMaxDynamicSharedMemorySize, K2_SMEM);
    cudaFuncSetAttribute(k3_leaf, cudaFuncAttributeMaxDynamicSharedMemorySize, K1_SMEM);

    convert_x<<< (Brows * DDIM / 4 + 255) / 256, 256 >>>(x);
    repack_b <<< (NPAD * KEFF + 255) / 256, 256 >>>(nw);
    repack_lb<<< (ODIM * KEFF2 + 255) / 256, 256 >>>(lw);
    k1_tc    <<< dim3(Brows / 128, NPAD / 128), 256, K1_SMEM >>>();
    k2_route <<< Brows / K2_ROWS, 256, K2_SMEM >>>();
    k3_leaf  <<< Brows / 128, 256, K1_SMEM >>>(out);
}

// round 6
// speedup vs baseline: 2.2133x; 1.0180x over previous
#include <cuda_runtime.h>
#include <cuda_bf16.h>
#include <cstdint>

// Problem constants
#define BMAXR 32768
#define DDIM  1024
#define TTREE 8
#define NODES 63
#define LEAVES 64
#define NPAD  512
#define ODIM  128
#define KEFF  3072     // 3 * DDIM (hi*hi, hi*lo, lo*hi)
#define KEFF2 1536     // 3 * NPAD for leaf GEMM

// Scratch (static device globals -- no runtime allocation)
__device__ __align__(256) float          g_s[(size_t)BMAXR * NPAD];
__device__ __align__(256) __nv_bfloat16  g_xhi[(size_t)BMAXR * DDIM];
__device__ __align__(256) __nv_bfloat16  g_xlo[(size_t)BMAXR * DDIM];
__device__ __align__(256) __nv_bfloat16  g_Bt[(size_t)NPAD * KEFF];   // [n][k3] parts: hi, lo, hi
__device__ __align__(256) __nv_bfloat16  g_muh[(size_t)BMAXR * NPAD];
__device__ __align__(256) __nv_bfloat16  g_mul[(size_t)BMAXR * NPAD];
__device__ __align__(256) __nv_bfloat16  g_LB[(size_t)ODIM * KEFF2];  // [o][k3] parts: hi, hi, lo

// ===========================================================================
// PTX helpers (all arch-generic: sm_80+ / sm_75+)
// ===========================================================================
__device__ __forceinline__ uint32_t smem_u32(const void* p) {
    uint32_t a;
    asm("{ .reg .u64 t; cvta.to.shared.u64 t, %1; cvt.u32.u64 %0, t; }"
        : "=r"(a) : "l"(p));
    return a;
}
__device__ __forceinline__ void cp16(uint32_t dst, const void* src) {
    asm volatile("cp.async.cg.shared.global [%0], [%1], 16;"
                 :: "r"(dst), "l"(src) : "memory");
}
#define CP_COMMIT() asm volatile("cp.async.commit_group;" ::: "memory")
#define CP_WAIT(n)  asm volatile("cp.async.wait_group %0;" :: "n"(n) : "memory")

__device__ __forceinline__ void ldsm4(uint32_t& r0, uint32_t& r1,
                                      uint32_t& r2, uint32_t& r3, uint32_t addr) {
    asm volatile("ldmatrix.sync.aligned.m8n8.x4.shared.b16 {%0,%1,%2,%3}, [%4];"
                 : "=r"(r0), "=r"(r1), "=r"(r2), "=r"(r3) : "r"(addr));
}
__device__ __forceinline__ void mma16816(float* d, const uint32_t* a,
                                         const uint32_t* b) {
    asm volatile("mma.sync.aligned.m16n8k16.row.col.f32.bf16.bf16.f32 "
                 "{%0,%1,%2,%3},{%4,%5,%6,%7},{%8,%9},{%0,%1,%2,%3};"
                 : "+f"(d[0]), "+f"(d[1]), "+f"(d[2]), "+f"(d[3])
                 : "r"(a[0]), "r"(a[1]), "r"(a[2]), "r"(a[3]),
                   "r"(b[0]), "r"(b[1]));
}

__device__ __forceinline__ float smooth_step(float u) {
    if (u <= -0.5f) return 0.0f;
    if (u >= 0.5f)  return 1.0f;
    return -2.0f * u * u * u + 1.5f * u + 0.5f;
}

// ===========================================================================
// Pre-pass kernels
// ===========================================================================
__global__ void convert_x(const float* __restrict__ x) {
    int i = blockIdx.x * blockDim.x + threadIdx.x;     // over n/4 float4
    float4 v = ((const float4*)x)[i];
    __nv_bfloat16 h[4], l[4];
    float f[4] = {v.x, v.y, v.z, v.w};
    #pragma unroll
    for (int j = 0; j < 4; j++) {
        h[j] = __float2bfloat16(f[j]);
        l[j] = __float2bfloat16(f[j] - __bfloat162float(h[j]));
    }
    *(uint64_t*)&g_xhi[(size_t)i * 4] = *(uint64_t*)h;
    *(uint64_t*)&g_xlo[(size_t)i * 4] = *(uint64_t*)l;
}

__global__ void repack_b(const float* __restrict__ nw) {
    int idx = blockIdx.x * blockDim.x + threadIdx.x;   // over NPAD*KEFF
    if (idx >= NPAD * KEFF) return;
    int n = idx / KEFF, k3 = idx % KEFF;
    int t = n >> 6, i = n & 63;
    int part = k3 >> 10, k = k3 & 1023;
    float w = 0.0f;
    if (i < NODES) w = nw[((size_t)t * DDIM + k) * NODES + i];
    __nv_bfloat16 hi = __float2bfloat16(w);
    __nv_bfloat16 outv = (part == 1) ? __float2bfloat16(w - __bfloat162float(hi)) : hi;
    g_Bt[idx] = outv;
}

// leaf weights -> [o][k3] bf16, k3 = part*512 + t*64 + l; parts: hi, hi, lo
__global__ void repack_lb(const float* __restrict__ lw) {
    int idx = blockIdx.x * blockDim.x + threadIdx.x;   // over ODIM*KEFF2
    if (idx >= ODIM * KEFF2) return;
    int o = idx / KEFF2, k3 = idx % KEFF2;
    int part = k3 >> 9, k = k3 & 511;
    int t = k >> 6, l = k & 63;
    float w = lw[((size_t)t * ODIM + o) * LEAVES + l];
    __nv_bfloat16 hi = __float2bfloat16(w);
    __nv_bfloat16 outv = (part == 2) ? __float2bfloat16(w - __bfloat162float(hi)) : hi;
    g_LB[idx] = outv;
}

// ===========================================================================
// K1: bf16 mma.sync GEMM  C[B x 512] = A[B x 3072] * Bt[512 x 3072]^T
// CTA tile 128x128, 8 warps x (64x32), K chunk 64, 3-stage cp.async,
// ONE barrier per chunk.  Chunk order (k_idx, sub): sub0 = Ahi*Bhi,
// sub1 = Ahi*Blo, sub2 = Alo*Bhi -- consecutive A-hi reads hit cache.
// bn = blockIdx.x (fastest) so concurrent CTAs share A slices in L2.
// ===========================================================================
#define A_ST 72
#define A_BYTES (128 * A_ST * 2)
#define STAGE_BYTES (2 * A_BYTES)
#define K1_STAGES 3
#define NCHUNK 48
#define K1_SMEM (K1_STAGES * STAGE_BYTES)

__global__ __launch_bounds__(256, 2) void k1_tc() {
    extern __shared__ char smraw[];
    const uint32_t smb = smem_u32(smraw);

    const int tid  = threadIdx.x;
    const int lane = tid & 31;
    const int wid  = tid >> 5;
    const int bn   = blockIdx.x;          // fastest: 4 bn CTAs share A rows
    const int bm   = blockIdx.y;
    const int wm   = (wid & 1) * 64;
    const int wn   = (wid >> 1) * 32;

    auto load_stage = [&](int c) {
        const int slot = c % K1_STAGES;
        const uint32_t sa = smb + slot * STAGE_BYTES;
        const uint32_t sb = sa + A_BYTES;
        const int sub   = c % 3;                       // term index
        const int k_idx = c / 3;                       // 0..15
        const __nv_bfloat16* ap = (sub == 2) ? g_xlo : g_xhi;
        const __nv_bfloat16* abase = ap + (size_t)bm * 128 * DDIM + k_idx * 64;
        const __nv_bfloat16* bbase = g_Bt + (size_t)bn * 128 * KEFF
                                     + (size_t)sub * 1024 + k_idx * 64;
        #pragma unroll
        for (int i = 0; i < 4; i++) {
            int u = tid + 256 * i;
            int row = u >> 3, seg = u & 7;
            cp16(sa + (uint32_t)(row * A_ST + seg * 8) * 2,
                 abase + (size_t)row * DDIM + seg * 8);
        }
        #pragma unroll
        for (int i = 0; i < 4; i++) {
            int u = tid + 256 * i;
            int row = u >> 3, seg = u & 7;
            cp16(sb + (uint32_t)(row * A_ST + seg * 8) * 2,
                 bbase + (size_t)row * KEFF + seg * 8);
        }
        CP_COMMIT();
    };

    float acc[4][4][4];
    #pragma unroll
    for (int t = 0; t < 4; t++)
        #pragma unroll
        for (int g = 0; g < 4; g++)
            #pragma unroll
            for (int e = 0; e < 4; e++) acc[t][g][e] = 0.0f;

    load_stage(0);
    load_stage(1);

    const int a_m   = (lane & 15);
    const int a_k8  = (lane >> 4) * 8;
    const int b_n   = ((lane >> 4) << 3) + (lane & 7);
    const int b_k8  = ((lane >> 3) & 1) * 8;

    for (int c = 0; c < NCHUNK; ++c) {
        if (c == NCHUNK - 1) { CP_WAIT(0); } else { CP_WAIT(1); }
        __syncthreads();
        // all warps finished compute(c-1) -> safe to refill slot (c+2)%3
        if (c + 2 < NCHUNK) load_stage(c + 2);

        const int slot = c % K1_STAGES;
        const uint32_t sa = smb + slot * STAGE_BYTES;
        const uint32_t sb = sa + A_BYTES;

        #pragma unroll
        for (int kk = 0; kk < 4; kk++) {
            uint32_t af[4][4];
            #pragma unroll
            for (int t = 0; t < 4; t++) {
                int m = wm + t * 16 + a_m;
                ldsm4(af[t][0], af[t][1], af[t][2], af[t][3],
                      sa + (uint32_t)(m * A_ST + kk * 16 + a_k8) * 2);
            }
            uint32_t bf[2][4];
            #pragma unroll
            for (int g16 = 0; g16 < 2; g16++) {
                int n = wn + g16 * 16 + b_n;
                ldsm4(bf[g16][0], bf[g16][1], bf[g16][2], bf[g16][3],
                      sb + (uint32_t)(n * A_ST + kk * 16 + b_k8) * 2);
            }
            #pragma unroll
            for (int t = 0; t < 4; t++)
                #pragma unroll
                for (int g = 0; g < 4; g++)
                    mma16816(acc[t][g], af[t], &bf[g >> 1][(g & 1) * 2]);
        }
    }
    __syncthreads();

    float* cs = (float*)smraw;          // [128][132]
    const int r0 = lane >> 2;
    const int c0 = (lane & 3) * 2;
    #pragma unroll
    for (int t = 0; t < 4; t++) {
        #pragma unroll
        for (int g = 0; g < 4; g++) {
            int m = wm + t * 16 + r0;
            int n = wn + g * 8 + c0;
            cs[m * 132 + n]           = smooth_step(acc[t][g][0]);
            cs[m * 132 + n + 1]       = smooth_step(acc[t][g][1]);
            cs[(m + 8) * 132 + n]     = smooth_step(acc[t][g][2]);
            cs[(m + 8) * 132 + n + 1] = smooth_step(acc[t][g][3]);
        }
    }
    __syncthreads();

    {
        const int row  = tid >> 1;
        const int half = tid & 1;
        float4* dst = (float4*)(g_s + ((size_t)bm * 128 + row) * NPAD
                                + bn * 128 + half * 64);
        const float* srcr = cs + row * 132 + half * 64;
        #pragma unroll
        for (int j = 0; j < 16; j++)
            dst[j] = *(const float4*)(srcr + j * 4);
    }
}

// ===========================================================================
// K2a: routing only.  Stage s transposed in smem, route in regs, write mu
// as bf16 hi/lo split (contiguous 128B per thread).
// ===========================================================================
#define K2_ROWS 32
#define ST 33
#define K2_SMEM (512 * ST * 4)    // 67584

__global__ __launch_bounds__(256) void k2_route() {
    extern __shared__ float st_s[];   // [512][33] transposed s

    const int tid = threadIdx.x;
    const size_t bbase = (size_t)blockIdx.x * K2_ROWS;

    {
        const float4* xsrc = (const float4*)(g_s + bbase * NPAD);
        #pragma unroll
        for (int i = 0; i < 16; i++) {
            int u = tid + 256 * i;           // 0..4095
            int row = u >> 7, c4 = u & 127;
            float4 v = xsrc[row * 128 + c4];
            st_s[(c4 * 4 + 0) * ST + row] = v.x;
            st_s[(c4 * 4 + 1) * ST + row] = v.y;
            st_s[(c4 * 4 + 2) * ST + row] = v.z;
            st_s[(c4 * 4 + 3) * ST + row] = v.w;
        }
    }
    __syncthreads();

    {
        const int row  = tid & 31;
        const int tree = tid >> 5;
        const float* sc = st_s + (size_t)tree * 64 * ST + row;

        float m[64];
        m[0] = 1.0f;
        int start = 0;
        #pragma unroll
        for (int lvl = 0; lvl < 6; ++lvl) {
            const int w = 1 << lvl;
            #pragma unroll
            for (int j = w - 1; j >= 0; --j) {
                float sv = sc[(start + j) * ST];
                float p  = m[j];
                m[2 * j]     = p * sv;
                m[2 * j + 1] = p * (1.0f - sv);
            }
            start += w;
        }

        const size_t obase = (bbase + row) * NPAD + tree * 64;
        #pragma unroll
        for (int g = 0; g < 8; ++g) {
            __nv_bfloat16 hb[8], lb[8];
            #pragma unroll
            for (int i = 0; i < 8; ++i) {
                float v = m[g * 8 + i];
                hb[i] = __float2bfloat16(v);
                lb[i] = __float2bfloat16(v - __bfloat162float(hb[i]));
            }
            *(uint4*)(g_muh + obase + g * 8) = *(uint4*)hb;
            *(uint4*)(g_mul + obase + g * 8) = *(uint4*)lb;
        }
    }
}

// ===========================================================================
// K3: leaf GEMM on tensor cores.
// out[B x 128] = sum of muh*LWhi + mul*LWhi + muh*LWlo   (K groups of 64)
// sub0: A=muh, B part0 (hi); sub1: A=mul, B part1 (hi); sub2: A=muh, B part2 (lo)
// ===========================================================================
#define NCHUNK3 24

__global__ __launch_bounds__(256, 2) void k3_leaf(float* __restrict__ out) {
    extern __shared__ char smraw[];
    const uint32_t smb = smem_u32(smraw);

    const int tid  = threadIdx.x;
    const int lane = tid & 31;
    const int wid  = tid >> 5;
    const int bm   = blockIdx.x;
    const int wm   = (wid & 1) * 64;
    const int wn   = (wid >> 1) * 32;

    auto load_stage = [&](int c) {
        const int slot = c % K1_STAGES;
        const uint32_t sa = smb + slot * STAGE_BYTES;
        const uint32_t sb = sa + A_BYTES;
        const int sub   = c % 3;
        const int k_idx = c / 3;                       // 0..7
        const __nv_bfloat16* ap = (sub == 1) ? g_mul : g_muh;
        const __nv_bfloat16* abase = ap + (size_t)bm * 128 * NPAD + k_idx * 64;
        const __nv_bfloat16* bbase = g_LB + (size_t)sub * 512 + k_idx * 64;
        #pragma unroll
        for (int i = 0; i < 4; i++) {
            int u = tid + 256 * i;
            int row = u >> 3, seg = u & 7;
            cp16(sa + (uint32_t)(row * A_ST + seg * 8) * 2,
                 abase + (size_t)row * NPAD + seg * 8);
        }
        #pragma unroll
        for (int i = 0; i < 4; i++) {
            int u = tid + 256 * i;
            int row = u >> 3, seg = u & 7;
            cp16(sb + (uint32_t)(row * A_ST + seg * 8) * 2,
                 bbase + (size_t)row * KEFF2 + seg * 8);
        }
        CP_COMMIT();
    };

    float acc[4][4][4];
    #pragma unroll
    for (int t = 0; t < 4; t++)
        #pragma unroll
        for (int g = 0; g < 4; g++)
            #pragma unroll
            for (int e = 0; e < 4; e++) acc[t][g][e] = 0.0f;

    load_stage(0);
    load_stage(1);

    const int a_m   = (lane & 15);
    const int a_k8  = (lane >> 4) * 8;
    const int b_n   = ((lane >> 4) << 3) + (lane & 7);
    const int b_k8  = ((lane >> 3) & 1) * 8;

    for (int c = 0; c < NCHUNK3; ++c) {
        if (c == NCHUNK3 - 1) { CP_WAIT(0); } else { CP_WAIT(1); }
        __syncthreads();
        if (c + 2 < NCHUNK3) load_stage(c + 2);

        const int slot = c % K1_STAGES;
        const uint32_t sa = smb + slot * STAGE_BYTES;
        const uint32_t sb = sa + A_BYTES;

        #pragma unroll
        for (int kk = 0; kk < 4; kk++) {
            uint32_t af[4][4];
            #pragma unroll
            for (int t = 0; t < 4; t++) {
                int m = wm + t * 16 + a_m;
                ldsm4(af[t][0], af[t][1], af[t][2], af[t][3],
                      sa + (uint32_t)(m * A_ST + kk * 16 + a_k8) * 2);
            }
            uint32_t bf[2][4];
            #pragma unroll
            for (int g16 = 0; g16 < 2; g16++) {
                int n = wn + g16 * 16 + b_n;
                ldsm4(bf[g16][0], bf[g16][1], bf[g16][2], bf[g16][3],
                      sb + (uint32_t)(n * A_ST + kk * 16 + b_k8) * 2);
            }
            #pragma unroll
            for (int t = 0; t < 4; t++)
                #pragma unroll
                for (int g = 0; g < 4; g++)
                    mma16816(acc[t][g], af[t], &bf[g >> 1][(g & 1) * 2]);
        }
    }
    __syncthreads();

    float* cs = (float*)smraw;          // [128][132]
    const int r0 = lane >> 2;
    const int c0 = (lane & 3) * 2;
    #pragma unroll
    for (int t = 0; t < 4; t++) {
        #pragma unroll
        for (int g = 0; g < 4; g++) {
            int m = wm + t * 16 + r0;
            int n = wn + g * 8 + c0;
            cs[m * 132 + n]           = acc[t][g][0];
            cs[m * 132 + n + 1]       = acc[t][g][1];
            cs[(m + 8) * 132 + n]     = acc[t][g][2];
            cs[(m + 8) * 132 + n + 1] = acc[t][g][3];
        }
    }
    __syncthreads();

    {
        const int row  = tid >> 1;
        const int half = tid & 1;
        float4* dst = (float4*)(out + ((size_t)bm * 128 + row) * ODIM + half * 64);
        const float* srcr = cs + row * 132 + half * 64;
        #pragma unroll
        for (int j = 0; j < 16; j++)
            dst[j] = *(const float4*)(srcr + j * 4);
    }
}

// ===========================================================================
// Launch
// ===========================================================================
extern "C" void kernel_launch(void* const* d_in, const int* in_sizes, int n_in,
                              void* d_out, int out_size) {
    const float* x  = (const float*)d_in[0];   // [B, 1024]
    const float* nw = (const float*)d_in[1];   // [8, 1024, 63]
    const float* lw = (const float*)d_in[2];   // [8, 128, 64]
    float* out = (float*)d_out;                // [B, 128]

    int Brows = in_sizes[0] / DDIM;            // 32768

    cudaFuncSetAttribute(k1_tc,   cudaFuncAttributeMaxDynamicSharedMemorySize, K1_SMEM);
    cudaFuncSetAttribute(k2_route,cudaFuncAttributeMaxDynamicSharedMemorySize, K2_SMEM);
    cudaFuncSetAttribute(k3_leaf, cudaFuncAttributeMaxDynamicSharedMemorySize, K1_SMEM);

    convert_x<<< (Brows * DDIM / 4 + 255) / 256, 256 >>>(x);
    repack_b <<< (NPAD * KEFF + 255) / 256, 256 >>>(nw);
    repack_lb<<< (ODIM * KEFF2 + 255) / 256, 256 >>>(lw);
    k1_tc    <<< dim3(NPAD / 128, Brows / 128), 256, K1_SMEM >>>();
    k2_route <<< Brows / K2_ROWS, 256, K2_SMEM >>>();
    k3_leaf  <<< Brows / 128, 256, K1_SMEM >>>(out);
}

// round 7
// speedup vs baseline: 3.7376x; 1.6887x over previous
#include <cuda_runtime.h>
#include <cuda_bf16.h>
#include <cuda_fp16.h>
#include <cstdint>

// Problem constants
#define BMAXR 32768
#define DDIM  1024
#define TTREE 8
#define NODES 63
#define LEAVES 64
#define NPAD  512
#define ODIM  128
#define KEFF2 1536     // 3 * NPAD for leaf GEMM (bf16 split, unchanged)

// Scratch (static device globals -- no runtime allocation)
__device__ __align__(256) float          g_s[(size_t)BMAXR * NPAD];
__device__ __align__(256) __half         g_xh[(size_t)BMAXR * DDIM];       // fp16 x
__device__ __align__(256) __half         g_Bt[(size_t)NPAD * DDIM];        // fp16 W [n][k]
__device__ __align__(256) __nv_bfloat16  g_muh[(size_t)BMAXR * NPAD];
__device__ __align__(256) __nv_bfloat16  g_mul[(size_t)BMAXR * NPAD];
__device__ __align__(256) __nv_bfloat16  g_LB[(size_t)ODIM * KEFF2];       // [o][k3] parts: hi, hi, lo

// ===========================================================================
// PTX helpers (all arch-generic: sm_80+ / sm_75+)
// ===========================================================================
__device__ __forceinline__ uint32_t smem_u32(const void* p) {
    uint32_t a;
    asm("{ .reg .u64 t; cvta.to.shared.u64 t, %1; cvt.u32.u64 %0, t; }"
        : "=r"(a) : "l"(p));
    return a;
}
__device__ __forceinline__ void cp16(uint32_t dst, const void* src) {
    asm volatile("cp.async.cg.shared.global [%0], [%1], 16;"
                 :: "r"(dst), "l"(src) : "memory");
}
#define CP_COMMIT() asm volatile("cp.async.commit_group;" ::: "memory")
#define CP_WAIT(n)  asm volatile("cp.async.wait_group %0;" :: "n"(n) : "memory")

__device__ __forceinline__ void ldsm4(uint32_t& r0, uint32_t& r1,
                                      uint32_t& r2, uint32_t& r3, uint32_t addr) {
    asm volatile("ldmatrix.sync.aligned.m8n8.x4.shared.b16 {%0,%1,%2,%3}, [%4];"
                 : "=r"(r0), "=r"(r1), "=r"(r2), "=r"(r3) : "r"(addr));
}
// bf16 variant (k3)
__device__ __forceinline__ void mma16816(float* d, const uint32_t* a,
                                         const uint32_t* b) {
    asm volatile("mma.sync.aligned.m16n8k16.row.col.f32.bf16.bf16.f32 "
                 "{%0,%1,%2,%3},{%4,%5,%6,%7},{%8,%9},{%0,%1,%2,%3};"
                 : "+f"(d[0]), "+f"(d[1]), "+f"(d[2]), "+f"(d[3])
                 : "r"(a[0]), "r"(a[1]), "r"(a[2]), "r"(a[3]),
                   "r"(b[0]), "r"(b[1]));
}
// fp16 variant (k1)
__device__ __forceinline__ void mma16816h(float* d, const uint32_t* a,
                                          const uint32_t* b) {
    asm volatile("mma.sync.aligned.m16n8k16.row.col.f32.f16.f16.f32 "
                 "{%0,%1,%2,%3},{%4,%5,%6,%7},{%8,%9},{%0,%1,%2,%3};"
                 : "+f"(d[0]), "+f"(d[1]), "+f"(d[2]), "+f"(d[3])
                 : "r"(a[0]), "r"(a[1]), "r"(a[2]), "r"(a[3]),
                   "r"(b[0]), "r"(b[1]));
}

__device__ __forceinline__ float smooth_step(float u) {
    if (u <= -0.5f) return 0.0f;
    if (u >= 0.5f)  return 1.0f;
    return -2.0f * u * u * u + 1.5f * u + 0.5f;
}

// ===========================================================================
// Pre-pass kernels
// ===========================================================================
__global__ void convert_x(const float* __restrict__ x) {
    int i = blockIdx.x * blockDim.x + threadIdx.x;     // over n/4 float4
    float4 v = ((const float4*)x)[i];
    __half h[4];
    h[0] = __float2half(v.x); h[1] = __float2half(v.y);
    h[2] = __float2half(v.z); h[3] = __float2half(v.w);
    *(uint64_t*)&g_xh[(size_t)i * 4] = *(uint64_t*)h;
}

__global__ void repack_b(const float* __restrict__ nw) {
    int idx = blockIdx.x * blockDim.x + threadIdx.x;   // over NPAD*DDIM
    if (idx >= NPAD * DDIM) return;
    int n = idx / DDIM, k = idx % DDIM;
    int t = n >> 6, i = n & 63;
    float w = 0.0f;
    if (i < NODES) w = nw[((size_t)t * DDIM + k) * NODES + i];
    g_Bt[idx] = __float2half(w);
}

// leaf weights -> [o][k3] bf16, k3 = part*512 + t*64 + l; parts: hi, hi, lo
__global__ void repack_lb(const float* __restrict__ lw) {
    int idx = blockIdx.x * blockDim.x + threadIdx.x;   // over ODIM*KEFF2
    if (idx >= ODIM * KEFF2) return;
    int o = idx / KEFF2, k3 = idx % KEFF2;
    int part = k3 >> 9, k = k3 & 511;
    int t = k >> 6, l = k & 63;
    float w = lw[((size_t)t * ODIM + o) * LEAVES + l];
    __nv_bfloat16 hi = __float2bfloat16(w);
    __nv_bfloat16 outv = (part == 2) ? __float2bfloat16(w - __bfloat162float(hi)) : hi;
    g_LB[idx] = outv;
}

// ===========================================================================
// K1: fp16 mma.sync GEMM  C[B x 512] = x[B x 1024] * W[512 x 1024]^T
// CTA tile 128x128, 8 warps x (64x32), K chunk 64, 3-stage cp.async,
// one barrier per chunk.  bn fastest -> concurrent CTAs share A in L2.
// ===========================================================================
#define A_ST 72
#define A_BYTES (128 * A_ST * 2)
#define STAGE_BYTES (2 * A_BYTES)
#define K1_STAGES 3
#define NCHUNK 16
#define K1_SMEM (K1_STAGES * STAGE_BYTES)

__global__ __launch_bounds__(256, 2) void k1_tc() {
    extern __shared__ char smraw[];
    const uint32_t smb = smem_u32(smraw);

    const int tid  = threadIdx.x;
    const int lane = tid & 31;
    const int wid  = tid >> 5;
    const int bn   = blockIdx.x;          // fastest: 4 bn CTAs share A rows
    const int bm   = blockIdx.y;
    const int wm   = (wid & 1) * 64;
    const int wn   = (wid >> 1) * 32;

    auto load_stage = [&](int c) {
        const int slot = c % K1_STAGES;
        const uint32_t sa = smb + slot * STAGE_BYTES;
        const uint32_t sb = sa + A_BYTES;
        const __half* abase = g_xh + (size_t)bm * 128 * DDIM + c * 64;
        const __half* bbase = g_Bt + (size_t)bn * 128 * DDIM + c * 64;
        #pragma unroll
        for (int i = 0; i < 4; i++) {
            int u = tid + 256 * i;
            int row = u >> 3, seg = u & 7;
            cp16(sa + (uint32_t)(row * A_ST + seg * 8) * 2,
                 abase + (size_t)row * DDIM + seg * 8);
        }
        #pragma unroll
        for (int i = 0; i < 4; i++) {
            int u = tid + 256 * i;
            int row = u >> 3, seg = u & 7;
            cp16(sb + (uint32_t)(row * A_ST + seg * 8) * 2,
                 bbase + (size_t)row * DDIM + seg * 8);
        }
        CP_COMMIT();
    };

    float acc[4][4][4];
    #pragma unroll
    for (int t = 0; t < 4; t++)
        #pragma unroll
        for (int g = 0; g < 4; g++)
            #pragma unroll
            for (int e = 0; e < 4; e++) acc[t][g][e] = 0.0f;

    load_stage(0);
    load_stage(1);

    const int a_m   = (lane & 15);
    const int a_k8  = (lane >> 4) * 8;
    const int b_n   = ((lane >> 4) << 3) + (lane & 7);
    const int b_k8  = ((lane >> 3) & 1) * 8;

    for (int c = 0; c < NCHUNK; ++c) {
        if (c == NCHUNK - 1) { CP_WAIT(0); } else { CP_WAIT(1); }
        __syncthreads();
        if (c + 2 < NCHUNK) load_stage(c + 2);

        const int slot = c % K1_STAGES;
        const uint32_t sa = smb + slot * STAGE_BYTES;
        const uint32_t sb = sa + A_BYTES;

        #pragma unroll
        for (int kk = 0; kk < 4; kk++) {
            uint32_t af[4][4];
            #pragma unroll
            for (int t = 0; t < 4; t++) {
                int m = wm + t * 16 + a_m;
                ldsm4(af[t][0], af[t][1], af[t][2], af[t][3],
                      sa + (uint32_t)(m * A_ST + kk * 16 + a_k8) * 2);
            }
            uint32_t bf[2][4];
            #pragma unroll
            for (int g16 = 0; g16 < 2; g16++) {
                int n = wn + g16 * 16 + b_n;
                ldsm4(bf[g16][0], bf[g16][1], bf[g16][2], bf[g16][3],
                      sb + (uint32_t)(n * A_ST + kk * 16 + b_k8) * 2);
            }
            #pragma unroll
            for (int t = 0; t < 4; t++)
                #pragma unroll
                for (int g = 0; g < 4; g++)
                    mma16816h(acc[t][g], af[t], &bf[g >> 1][(g & 1) * 2]);
        }
    }
    __syncthreads();

    float* cs = (float*)smraw;          // [128][132]
    const int r0 = lane >> 2;
    const int c0 = (lane & 3) * 2;
    #pragma unroll
    for (int t = 0; t < 4; t++) {
        #pragma unroll
        for (int g = 0; g < 4; g++) {
            int m = wm + t * 16 + r0;
            int n = wn + g * 8 + c0;
            cs[m * 132 + n]           = smooth_step(acc[t][g][0]);
            cs[m * 132 + n + 1]       = smooth_step(acc[t][g][1]);
            cs[(m + 8) * 132 + n]     = smooth_step(acc[t][g][2]);
            cs[(m + 8) * 132 + n + 1] = smooth_step(acc[t][g][3]);
        }
    }
    __syncthreads();

    {
        const int row  = tid >> 1;
        const int half = tid & 1;
        float4* dst = (float4*)(g_s + ((size_t)bm * 128 + row) * NPAD
                                + bn * 128 + half * 64);
        const float* srcr = cs + row * 132 + half * 64;
        #pragma unroll
        for (int j = 0; j < 16; j++)
            dst[j] = *(const float4*)(srcr + j * 4);
    }
}

// ===========================================================================
// K2a: routing only.  Stage s transposed in smem, route in regs, write mu
// as bf16 hi/lo split (contiguous 128B per thread).
// ===========================================================================
#define K2_ROWS 32
#define ST 33
#define K2_SMEM (512 * ST * 4)    // 67584

__global__ __launch_bounds__(256) void k2_route() {
    extern __shared__ float st_s[];   // [512][33] transposed s

    const int tid = threadIdx.x;
    const size_t bbase = (size_t)blockIdx.x * K2_ROWS;

    {
        const float4* xsrc = (const float4*)(g_s + bbase * NPAD);
        #pragma unroll
        for (int i = 0; i < 16; i++) {
            int u = tid + 256 * i;           // 0..4095
            int row = u >> 7, c4 = u & 127;
            float4 v = xsrc[row * 128 + c4];
            st_s[(c4 * 4 + 0) * ST + row] = v.x;
            st_s[(c4 * 4 + 1) * ST + row] = v.y;
            st_s[(c4 * 4 + 2) * ST + row] = v.z;
            st_s[(c4 * 4 + 3) * ST + row] = v.w;
        }
    }
    __syncthreads();

    {
        const int row  = tid & 31;
        const int tree = tid >> 5;
        const float* sc = st_s + (size_t)tree * 64 * ST + row;

        float m[64];
        m[0] = 1.0f;
        int start = 0;
        #pragma unroll
        for (int lvl = 0; lvl < 6; ++lvl) {
            const int w = 1 << lvl;
            #pragma unroll
            for (int j = w - 1; j >= 0; --j) {
                float sv = sc[(start + j) * ST];
                float p  = m[j];
                m[2 * j]     = p * sv;
                m[2 * j + 1] = p * (1.0f - sv);
            }
            start += w;
        }

        const size_t obase = (bbase + row) * NPAD + tree * 64;
        #pragma unroll
        for (int g = 0; g < 8; ++g) {
            __nv_bfloat16 hb[8], lb[8];
            #pragma unroll
            for (int i = 0; i < 8; ++i) {
                float v = m[g * 8 + i];
                hb[i] = __float2bfloat16(v);
                lb[i] = __float2bfloat16(v - __bfloat162float(hb[i]));
            }
            *(uint4*)(g_muh + obase + g * 8) = *(uint4*)hb;
            *(uint4*)(g_mul + obase + g * 8) = *(uint4*)lb;
        }
    }
}

// ===========================================================================
// K3: leaf GEMM on tensor cores (bf16 3-term, unchanged).
// out[B x 128] = muh*LWhi + mul*LWhi + muh*LWlo   (K groups of 64)
// ===========================================================================
#define NCHUNK3 24

__global__ __launch_bounds__(256, 2) void k3_leaf(float* __restrict__ out) {
    extern __shared__ char smraw[];
    const uint32_t smb = smem_u32(smraw);

    const int tid  = threadIdx.x;
    const int lane = tid & 31;
    const int wid  = tid >> 5;
    const int bm   = blockIdx.x;
    const int wm   = (wid & 1) * 64;
    const int wn   = (wid >> 1) * 32;

    auto load_stage = [&](int c) {
        const int slot = c % K1_STAGES;
        const uint32_t sa = smb + slot * STAGE_BYTES;
        const uint32_t sb = sa + A_BYTES;
        const int sub   = c % 3;
        const int k_idx = c / 3;                       // 0..7
        const __nv_bfloat16* ap = (sub == 1) ? g_mul : g_muh;
        const __nv_bfloat16* abase = ap + (size_t)bm * 128 * NPAD + k_idx * 64;
        const __nv_bfloat16* bbase = g_LB + (size_t)sub * 512 + k_idx * 64;
        #pragma unroll
        for (int i = 0; i < 4; i++) {
            int u = tid + 256 * i;
            int row = u >> 3, seg = u & 7;
            cp16(sa + (uint32_t)(row * A_ST + seg * 8) * 2,
                 abase + (size_t)row * NPAD + seg * 8);
        }
        #pragma unroll
        for (int i = 0; i < 4; i++) {
            int u = tid + 256 * i;
            int row = u >> 3, seg = u & 7;
            cp16(sb + (uint32_t)(row * A_ST + seg * 8) * 2,
                 bbase + (size_t)row * KEFF2 + seg * 8);
        }
        CP_COMMIT();
    };

    float acc[4][4][4];
    #pragma unroll
    for (int t = 0; t < 4; t++)
        #pragma unroll
        for (int g = 0; g < 4; g++)
            #pragma unroll
            for (int e = 0; e < 4; e++) acc[t][g][e] = 0.0f;

    load_stage(0);
    load_stage(1);

    const int a_m   = (lane & 15);
    const int a_k8  = (lane >> 4) * 8;
    const int b_n   = ((lane >> 4) << 3) + (lane & 7);
    const int b_k8  = ((lane >> 3) & 1) * 8;

    for (int c = 0; c < NCHUNK3; ++c) {
        if (c == NCHUNK3 - 1) { CP_WAIT(0); } else { CP_WAIT(1); }
        __syncthreads();
        if (c + 2 < NCHUNK3) load_stage(c + 2);

        const int slot = c % K1_STAGES;
        const uint32_t sa = smb + slot * STAGE_BYTES;
        const uint32_t sb = sa + A_BYTES;

        #pragma unroll
        for (int kk = 0; kk < 4; kk++) {
            uint32_t af[4][4];
            #pragma unroll
            for (int t = 0; t < 4; t++) {
                int m = wm + t * 16 + a_m;
                ldsm4(af[t][0], af[t][1], af[t][2], af[t][3],
                      sa + (uint32_t)(m * A_ST + kk * 16 + a_k8) * 2);
            }
            uint32_t bf[2][4];
            #pragma unroll
            for (int g16 = 0; g16 < 2; g16++) {
                int n = wn + g16 * 16 + b_n;
                ldsm4(bf[g16][0], bf[g16][1], bf[g16][2], bf[g16][3],
                      sb + (uint32_t)(n * A_ST + kk * 16 + b_k8) * 2);
            }
            #pragma unroll
            for (int t = 0; t < 4; t++)
                #pragma unroll
                for (int g = 0; g < 4; g++)
                    mma16816(acc[t][g], af[t], &bf[g >> 1][(g & 1) * 2]);
        }
    }
    __syncthreads();

    float* cs = (float*)smraw;          // [128][132]
    const int r0 = lane >> 2;
    const int c0 = (lane & 3) * 2;
    #pragma unroll
    for (int t = 0; t < 4; t++) {
        #pragma unroll
        for (int g = 0; g < 4; g++) {
            int m = wm + t * 16 + r0;
            int n = wn + g * 8 + c0;
            cs[m * 132 + n]           = acc[t][g][0];
            cs[m * 132 + n + 1]       = acc[t][g][1];
            cs[(m + 8) * 132 + n]     = acc[t][g][2];
            cs[(m + 8) * 132 + n + 1] = acc[t][g][3];
        }
    }
    __syncthreads();

    {
        const int row  = tid >> 1;
        const int half = tid & 1;
        float4* dst = (float4*)(out + ((size_t)bm * 128 + row) * ODIM + half * 64);
        const float* srcr = cs + row * 132 + half * 64;
        #pragma unroll
        for (int j = 0; j < 16; j++)
            dst[j] = *(const float4*)(srcr + j * 4);
    }
}

// ===========================================================================
// Launch
// ===========================================================================
extern "C" void kernel_launch(void* const* d_in, const int* in_sizes, int n_in,
                              void* d_out, int out_size) {
    const float* x  = (const float*)d_in[0];   // [B, 1024]
    const float* nw = (const float*)d_in[1];   // [8, 1024, 63]
    const float* lw = (const float*)d_in[2];   // [8, 128, 64]
    float* out = (float*)d_out;                // [B, 128]

    int Brows = in_sizes[0] / DDIM;            // 32768

    cudaFuncSetAttribute(k1_tc,   cudaFuncAttributeMaxDynamicSharedMemorySize, K1_SMEM);
    cudaFuncSetAttribute(k2_route,cudaFuncAttributeMaxDynamicSharedMemorySize, K2_SMEM);
    cudaFuncSetAttribute(k3_leaf, cudaFuncAttributeMaxDynamicSharedMemorySize, K1_SMEM);

    convert_x<<< (Brows * DDIM / 4 + 255) / 256, 256 >>>(x);
    repack_b <<< (NPAD * DDIM + 255) / 256, 256 >>>(nw);
    repack_lb<<< (ODIM * KEFF2 + 255) / 256, 256 >>>(lw);
    k1_tc    <<< dim3(NPAD / 128, Brows / 128), 256, K1_SMEM >>>();
    k2_route <<< Brows / K2_ROWS, 256, K2_SMEM >>>();
    k3_leaf  <<< Brows / 128, 256, K1_SMEM >>>(out);
}

// round 8
// speedup vs baseline: 4.2436x; 1.1354x over previous
#include <cuda_runtime.h>
#include <cuda_bf16.h>
#include <cuda_fp16.h>
#include <cstdint>

// Problem constants
#define BMAXR 32768
#define DDIM  1024
#define TTREE 8
#define NODES 63
#define LEAVES 64
#define NPAD  512
#define ODIM  128

// Scratch (static device globals -- no runtime allocation)
__device__ __align__(256) float   g_s[(size_t)BMAXR * NPAD];
__device__ __align__(256) __half  g_xh[(size_t)BMAXR * DDIM];     // fp16 x
__device__ __align__(256) __half  g_Bt[(size_t)NPAD * DDIM];      // fp16 W [n][k]
__device__ __align__(256) __half  g_mu[(size_t)BMAXR * NPAD];     // fp16 mu
__device__ __align__(256) __half  g_LBh[(size_t)ODIM * NPAD];     // fp16 LW [o][k]

// ===========================================================================
// PTX helpers (all arch-generic: sm_80+ / sm_75+)
// ===========================================================================
__device__ __forceinline__ uint32_t smem_u32(const void* p) {
    uint32_t a;
    asm("{ .reg .u64 t; cvta.to.shared.u64 t, %1; cvt.u32.u64 %0, t; }"
        : "=r"(a) : "l"(p));
    return a;
}
__device__ __forceinline__ void cp16(uint32_t dst, const void* src) {
    asm volatile("cp.async.cg.shared.global [%0], [%1], 16;"
                 :: "r"(dst), "l"(src) : "memory");
}
#define CP_COMMIT() asm volatile("cp.async.commit_group;" ::: "memory")
#define CP_WAIT(n)  asm volatile("cp.async.wait_group %0;" :: "n"(n) : "memory")

__device__ __forceinline__ void ldsm4(uint32_t& r0, uint32_t& r1,
                                      uint32_t& r2, uint32_t& r3, uint32_t addr) {
    asm volatile("ldmatrix.sync.aligned.m8n8.x4.shared.b16 {%0,%1,%2,%3}, [%4];"
                 : "=r"(r0), "=r"(r1), "=r"(r2), "=r"(r3) : "r"(addr));
}
// fp16 mma
__device__ __forceinline__ void mma16816h(float* d, const uint32_t* a,
                                          const uint32_t* b) {
    asm volatile("mma.sync.aligned.m16n8k16.row.col.f32.f16.f16.f32 "
                 "{%0,%1,%2,%3},{%4,%5,%6,%7},{%8,%9},{%0,%1,%2,%3};"
                 : "+f"(d[0]), "+f"(d[1]), "+f"(d[2]), "+f"(d[3])
                 : "r"(a[0]), "r"(a[1]), "r"(a[2]), "r"(a[3]),
                   "r"(b[0]), "r"(b[1]));
}

__device__ __forceinline__ float smooth_step(float u) {
    if (u <= -0.5f) return 0.0f;
    if (u >= 0.5f)  return 1.0f;
    return -2.0f * u * u * u + 1.5f * u + 0.5f;
}

// ===========================================================================
// Pre-pass kernels
// ===========================================================================
__global__ void convert_x(const float* __restrict__ x) {
    int i = blockIdx.x * blockDim.x + threadIdx.x;     // over n/4 float4
    float4 v = ((const float4*)x)[i];
    __half h[4];
    h[0] = __float2half(v.x); h[1] = __float2half(v.y);
    h[2] = __float2half(v.z); h[3] = __float2half(v.w);
    *(uint64_t*)&g_xh[(size_t)i * 4] = *(uint64_t*)h;
}

__global__ void repack_b(const float* __restrict__ nw) {
    int idx = blockIdx.x * blockDim.x + threadIdx.x;   // over NPAD*DDIM
    if (idx >= NPAD * DDIM) return;
    int n = idx / DDIM, k = idx % DDIM;
    int t = n >> 6, i = n & 63;
    float w = 0.0f;
    if (i < NODES) w = nw[((size_t)t * DDIM + k) * NODES + i];
    g_Bt[idx] = __float2half(w);
}

// leaf weights -> [o][k] fp16, k = t*64 + l
__global__ void repack_lb(const float* __restrict__ lw) {
    int idx = blockIdx.x * blockDim.x + threadIdx.x;   // over ODIM*NPAD
    if (idx >= ODIM * NPAD) return;
    int o = idx / NPAD, k = idx % NPAD;
    int t = k >> 6, l = k & 63;
    g_LBh[idx] = __float2half(lw[((size_t)t * ODIM + o) * LEAVES + l]);
}

// ===========================================================================
// K1: fp16 mma.sync GEMM  C[B x 512] = x[B x 1024] * W[512 x 1024]^T
// CTA tile 128x128, 8 warps x (64x32), K chunk 64, 3-stage cp.async,
// one barrier per chunk.  bn fastest -> concurrent CTAs share A in L2.
// ===========================================================================
#define A_ST 72
#define A_BYTES (128 * A_ST * 2)
#define STAGE_BYTES (2 * A_BYTES)
#define K1_STAGES 3
#define NCHUNK 16
#define K1_SMEM (K1_STAGES * STAGE_BYTES)

__global__ __launch_bounds__(256, 2) void k1_tc() {
    extern __shared__ char smraw[];
    const uint32_t smb = smem_u32(smraw);

    const int tid  = threadIdx.x;
    const int lane = tid & 31;
    const int wid  = tid >> 5;
    const int bn   = blockIdx.x;          // fastest: 4 bn CTAs share A rows
    const int bm   = blockIdx.y;
    const int wm   = (wid & 1) * 64;
    const int wn   = (wid >> 1) * 32;

    auto load_stage = [&](int c) {
        const int slot = c % K1_STAGES;
        const uint32_t sa = smb + slot * STAGE_BYTES;
        const uint32_t sb = sa + A_BYTES;
        const __half* abase = g_xh + (size_t)bm * 128 * DDIM + c * 64;
        const __half* bbase = g_Bt + (size_t)bn * 128 * DDIM + c * 64;
        #pragma unroll
        for (int i = 0; i < 4; i++) {
            int u = tid + 256 * i;
            int row = u >> 3, seg = u & 7;
            cp16(sa + (uint32_t)(row * A_ST + seg * 8) * 2,
                 abase + (size_t)row * DDIM + seg * 8);
        }
        #pragma unroll
        for (int i = 0; i < 4; i++) {
            int u = tid + 256 * i;
            int row = u >> 3, seg = u & 7;
            cp16(sb + (uint32_t)(row * A_ST + seg * 8) * 2,
                 bbase + (size_t)row * DDIM + seg * 8);
        }
        CP_COMMIT();
    };

    float acc[4][4][4];
    #pragma unroll
    for (int t = 0; t < 4; t++)
        #pragma unroll
        for (int g = 0; g < 4; g++)
            #pragma unroll
            for (int e = 0; e < 4; e++) acc[t][g][e] = 0.0f;

    load_stage(0);
    load_stage(1);

    const int a_m   = (lane & 15);
    const int a_k8  = (lane >> 4) * 8;
    const int b_n   = ((lane >> 4) << 3) + (lane & 7);
    const int b_k8  = ((lane >> 3) & 1) * 8;

    for (int c = 0; c < NCHUNK; ++c) {
        if (c == NCHUNK - 1) { CP_WAIT(0); } else { CP_WAIT(1); }
        __syncthreads();
        if (c + 2 < NCHUNK) load_stage(c + 2);

        const int slot = c % K1_STAGES;
        const uint32_t sa = smb + slot * STAGE_BYTES;
        const uint32_t sb = sa + A_BYTES;

        #pragma unroll
        for (int kk = 0; kk < 4; kk++) {
            uint32_t af[4][4];
            #pragma unroll
            for (int t = 0; t < 4; t++) {
                int m = wm + t * 16 + a_m;
                ldsm4(af[t][0], af[t][1], af[t][2], af[t][3],
                      sa + (uint32_t)(m * A_ST + kk * 16 + a_k8) * 2);
            }
            uint32_t bf[2][4];
            #pragma unroll
            for (int g16 = 0; g16 < 2; g16++) {
                int n = wn + g16 * 16 + b_n;
                ldsm4(bf[g16][0], bf[g16][1], bf[g16][2], bf[g16][3],
                      sb + (uint32_t)(n * A_ST + kk * 16 + b_k8) * 2);
            }
            #pragma unroll
            for (int t = 0; t < 4; t++)
                #pragma unroll
                for (int g = 0; g < 4; g++)
                    mma16816h(acc[t][g], af[t], &bf[g >> 1][(g & 1) * 2]);
        }
    }
    __syncthreads();

    float* cs = (float*)smraw;          // [128][132]
    const int r0 = lane >> 2;
    const int c0 = (lane & 3) * 2;
    #pragma unroll
    for (int t = 0; t < 4; t++) {
        #pragma unroll
        for (int g = 0; g < 4; g++) {
            int m = wm + t * 16 + r0;
            int n = wn + g * 8 + c0;
            cs[m * 132 + n]           = smooth_step(acc[t][g][0]);
            cs[m * 132 + n + 1]       = smooth_step(acc[t][g][1]);
            cs[(m + 8) * 132 + n]     = smooth_step(acc[t][g][2]);
            cs[(m + 8) * 132 + n + 1] = smooth_step(acc[t][g][3]);
        }
    }
    __syncthreads();

    {
        const int row  = tid >> 1;
        const int half = tid & 1;
        float4* dst = (float4*)(g_s + ((size_t)bm * 128 + row) * NPAD
                                + bn * 128 + half * 64);
        const float* srcr = cs + row * 132 + half * 64;
        #pragma unroll
        for (int j = 0; j < 16; j++)
            dst[j] = *(const float4*)(srcr + j * 4);
    }
}

// ===========================================================================
// K2a: routing only.  Stage s transposed in smem, route in regs, write mu
// as fp16 (contiguous 128B per thread).
// ===========================================================================
#define K2_ROWS 32
#define ST 33
#define K2_SMEM (512 * ST * 4)    // 67584

__global__ __launch_bounds__(256) void k2_route() {
    extern __shared__ float st_s[];   // [512][33] transposed s

    const int tid = threadIdx.x;
    const size_t bbase = (size_t)blockIdx.x * K2_ROWS;

    {
        const float4* xsrc = (const float4*)(g_s + bbase * NPAD);
        #pragma unroll
        for (int i = 0; i < 16; i++) {
            int u = tid + 256 * i;           // 0..4095
            int row = u >> 7, c4 = u & 127;
            float4 v = xsrc[row * 128 + c4];
            st_s[(c4 * 4 + 0) * ST + row] = v.x;
            st_s[(c4 * 4 + 1) * ST + row] = v.y;
            st_s[(c4 * 4 + 2) * ST + row] = v.z;
            st_s[(c4 * 4 + 3) * ST + row] = v.w;
        }
    }
    __syncthreads();

    {
        const int row  = tid & 31;
        const int tree = tid >> 5;
        const float* sc = st_s + (size_t)tree * 64 * ST + row;

        float m[64];
        m[0] = 1.0f;
        int start = 0;
        #pragma unroll
        for (int lvl = 0; lvl < 6; ++lvl) {
            const int w = 1 << lvl;
            #pragma unroll
            for (int j = w - 1; j >= 0; --j) {
                float sv = sc[(start + j) * ST];
                float p  = m[j];
                m[2 * j]     = p * sv;
                m[2 * j + 1] = p * (1.0f - sv);
            }
            start += w;
        }

        const size_t obase = (bbase + row) * NPAD + tree * 64;
        #pragma unroll
        for (int g = 0; g < 8; ++g) {
            __half hb[8];
            #pragma unroll
            for (int i = 0; i < 8; ++i)
                hb[i] = __float2half(m[g * 8 + i]);
            *(uint4*)(g_mu + obase + g * 8) = *(uint4*)hb;
        }
    }
}

// ===========================================================================
// K3: leaf GEMM on tensor cores (fp16 single-pass).
// out[B x 128] = mu[B x 512] * LW[128 x 512]^T
// ===========================================================================
#define NCHUNK3 8

__global__ __launch_bounds__(256, 2) void k3_leaf(float* __restrict__ out) {
    extern __shared__ char smraw[];
    const uint32_t smb = smem_u32(smraw);

    const int tid  = threadIdx.x;
    const int lane = tid & 31;
    const int wid  = tid >> 5;
    const int bm   = blockIdx.x;
    const int wm   = (wid & 1) * 64;
    const int wn   = (wid >> 1) * 32;

    auto load_stage = [&](int c) {
        const int slot = c % K1_STAGES;
        const uint32_t sa = smb + slot * STAGE_BYTES;
        const uint32_t sb = sa + A_BYTES;
        const __half* abase = g_mu + (size_t)bm * 128 * NPAD + c * 64;
        const __half* bbase = g_LBh + c * 64;
        #pragma unroll
        for (int i = 0; i < 4; i++) {
            int u = tid + 256 * i;
            int row = u >> 3, seg = u & 7;
            cp16(sa + (uint32_t)(row * A_ST + seg * 8) * 2,
                 abase + (size_t)row * NPAD + seg * 8);
        }
        #pragma unroll
        for (int i = 0; i < 4; i++) {
            int u = tid + 256 * i;
            int row = u >> 3, seg = u & 7;
            cp16(sb + (uint32_t)(row * A_ST + seg * 8) * 2,
                 bbase + (size_t)row * NPAD + seg * 8);
        }
        CP_COMMIT();
    };

    float acc[4][4][4];
    #pragma unroll
    for (int t = 0; t < 4; t++)
        #pragma unroll
        for (int g = 0; g < 4; g++)
            #pragma unroll
            for (int e = 0; e < 4; e++) acc[t][g][e] = 0.0f;

    load_stage(0);
    load_stage(1);

    const int a_m   = (lane & 15);
    const int a_k8  = (lane >> 4) * 8;
    const int b_n   = ((lane >> 4) << 3) + (lane & 7);
    const int b_k8  = ((lane >> 3) & 1) * 8;

    for (int c = 0; c < NCHUNK3; ++c) {
        if (c == NCHUNK3 - 1) { CP_WAIT(0); } else { CP_WAIT(1); }
        __syncthreads();
        if (c + 2 < NCHUNK3) load_stage(c + 2);

        const int slot = c % K1_STAGES;
        const uint32_t sa = smb + slot * STAGE_BYTES;
        const uint32_t sb = sa + A_BYTES;

        #pragma unroll
        for (int kk = 0; kk < 4; kk++) {
            uint32_t af[4][4];
            #pragma unroll
            for (int t = 0; t < 4; t++) {
                int m = wm + t * 16 + a_m;
                ldsm4(af[t][0], af[t][1], af[t][2], af[t][3],
                      sa + (uint32_t)(m * A_ST + kk * 16 + a_k8) * 2);
            }
            uint32_t bf[2][4];
            #pragma unroll
            for (int g16 = 0; g16 < 2; g16++) {
                int n = wn + g16 * 16 + b_n;
                ldsm4(bf[g16][0], bf[g16][1], bf[g16][2], bf[g16][3],
                      sb + (uint32_t)(n * A_ST + kk * 16 + b_k8) * 2);
            }
            #pragma unroll
            for (int t = 0; t < 4; t++)
                #pragma unroll
                for (int g = 0; g < 4; g++)
                    mma16816h(acc[t][g], af[t], &bf[g >> 1][(g & 1) * 2]);
        }
    }
    __syncthreads();

    float* cs = (float*)smraw;          // [128][132]
    const int r0 = lane >> 2;
    const int c0 = (lane & 3) * 2;
    #pragma unroll
    for (int t = 0; t < 4; t++) {
        #pragma unroll
        for (int g = 0; g < 4; g++) {
            int m = wm + t * 16 + r0;
            int n = wn + g * 8 + c0;
            cs[m * 132 + n]           = acc[t][g][0];
            cs[m * 132 + n + 1]       = acc[t][g][1];
            cs[(m + 8) * 132 + n]     = acc[t][g][2];
            cs[(m + 8) * 132 + n + 1] = acc[t][g][3];
        }
    }
    __syncthreads();

    {
        const int row  = tid >> 1;
        const int half = tid & 1;
        float4* dst = (float4*)(out + ((size_t)bm * 128 + row) * ODIM + half * 64);
        const float* srcr = cs + row * 132 + half * 64;
        #pragma unroll
        for (int j = 0; j < 16; j++)
            dst[j] = *(const float4*)(srcr + j * 4);
    }
}

// ===========================================================================
// Launch
// ===========================================================================
extern "C" void kernel_launch(void* const* d_in, const int* in_sizes, int n_in,
                              void* d_out, int out_size) {
    const float* x  = (const float*)d_in[0];   // [B, 1024]
    const float* nw = (const float*)d_in[1];   // [8, 1024, 63]
    const float* lw = (const float*)d_in[2];   // [8, 128, 64]
    float* out = (float*)d_out;                // [B, 128]

    int Brows = in_sizes[0] / DDIM;            // 32768

    cudaFuncSetAttribute(k1_tc,   cudaFuncAttributeMaxDynamicSharedMemorySize, K1_SMEM);
    cudaFuncSetAttribute(k2_route,cudaFuncAttributeMaxDynamicSharedMemorySize, K2_SMEM);
    cudaFuncSetAttribute(k3_leaf, cudaFuncAttributeMaxDynamicSharedMemorySize, K1_SMEM);

    convert_x<<< (Brows * DDIM / 4 + 255) / 256, 256 >>>(x);
    repack_b <<< (NPAD * DDIM + 255) / 256, 256 >>>(nw);
    repack_lb<<< (ODIM * NPAD + 255) / 256, 256 >>>(lw);
    k1_tc    <<< dim3(NPAD / 128, Brows / 128), 256, K1_SMEM >>>();
    k2_route <<< Brows / K2_ROWS, 256, K2_SMEM >>>();
    k3_leaf  <<< Brows / 128, 256, K1_SMEM >>>(out);
}

// round 9
// speedup vs baseline: 4.8611x; 1.1455x over previous
#include <cuda_runtime.h>
#include <cuda_bf16.h>
#include <cuda_fp16.h>
#include <cstdint>

// Problem constants
#define BMAXR 32768
#define DDIM  1024
#define TTREE 8
#define NODES 63
#define LEAVES 64
#define NPAD  512
#define ODIM  128

// Scratch (static device globals -- no runtime allocation)
__device__ __align__(256) __half  g_xh[(size_t)BMAXR * DDIM];     // fp16 x
__device__ __align__(256) __half  g_Bt[(size_t)NPAD * DDIM];      // fp16 W [n][k]
__device__ __align__(256) __half  g_mu[(size_t)BMAXR * NPAD];     // fp16 mu
__device__ __align__(256) __half  g_LBh[(size_t)ODIM * NPAD];     // fp16 LW [o][k]

// ===========================================================================
// PTX helpers (all arch-generic: sm_80+ / sm_75+)
// ===========================================================================
__device__ __forceinline__ uint32_t smem_u32(const void* p) {
    uint32_t a;
    asm("{ .reg .u64 t; cvta.to.shared.u64 t, %1; cvt.u32.u64 %0, t; }"
        : "=r"(a) : "l"(p));
    return a;
}
__device__ __forceinline__ void cp16(uint32_t dst, const void* src) {
    asm volatile("cp.async.cg.shared.global [%0], [%1], 16;"
                 :: "r"(dst), "l"(src) : "memory");
}
#define CP_COMMIT() asm volatile("cp.async.commit_group;" ::: "memory")
#define CP_WAIT(n)  asm volatile("cp.async.wait_group %0;" :: "n"(n) : "memory")

__device__ __forceinline__ void ldsm4(uint32_t& r0, uint32_t& r1,
                                      uint32_t& r2, uint32_t& r3, uint32_t addr) {
    asm volatile("ldmatrix.sync.aligned.m8n8.x4.shared.b16 {%0,%1,%2,%3}, [%4];"
                 : "=r"(r0), "=r"(r1), "=r"(r2), "=r"(r3) : "r"(addr));
}
// fp16 mma
__device__ __forceinline__ void mma16816h(float* d, const uint32_t* a,
                                          const uint32_t* b) {
    asm volatile("mma.sync.aligned.m16n8k16.row.col.f32.f16.f16.f32 "
                 "{%0,%1,%2,%3},{%4,%5,%6,%7},{%8,%9},{%0,%1,%2,%3};"
                 : "+f"(d[0]), "+f"(d[1]), "+f"(d[2]), "+f"(d[3])
                 : "r"(a[0]), "r"(a[1]), "r"(a[2]), "r"(a[3]),
                   "r"(b[0]), "r"(b[1]));
}

__device__ __forceinline__ float smooth_step(float u) {
    if (u <= -0.5f) return 0.0f;
    if (u >= 0.5f)  return 1.0f;
    return -2.0f * u * u * u + 1.5f * u + 0.5f;
}

// ===========================================================================
// Pre-pass kernels
// ===========================================================================
__global__ void convert_x(const float* __restrict__ x) {
    int i = blockIdx.x * blockDim.x + threadIdx.x;     // over n/4 float4
    float4 v = ((const float4*)x)[i];
    __half h[4];
    h[0] = __float2half(v.x); h[1] = __float2half(v.y);
    h[2] = __float2half(v.z); h[3] = __float2half(v.w);
    *(uint64_t*)&g_xh[(size_t)i * 4] = *(uint64_t*)h;
}

__global__ void repack_b(const float* __restrict__ nw) {
    int idx = blockIdx.x * blockDim.x + threadIdx.x;   // over NPAD*DDIM
    if (idx >= NPAD * DDIM) return;
    int n = idx / DDIM, k = idx % DDIM;
    int t = n >> 6, i = n & 63;
    float w = 0.0f;
    if (i < NODES) w = nw[((size_t)t * DDIM + k) * NODES + i];
    g_Bt[idx] = __float2half(w);
}

// leaf weights -> [o][k] fp16, k = t*64 + l
__global__ void repack_lb(const float* __restrict__ lw) {
    int idx = blockIdx.x * blockDim.x + threadIdx.x;   // over ODIM*NPAD
    if (idx >= ODIM * NPAD) return;
    int o = idx / NPAD, k = idx % NPAD;
    int t = k >> 6, l = k & 63;
    g_LBh[idx] = __float2half(lw[((size_t)t * ODIM + o) * LEAVES + l]);
}

// ===========================================================================
// K1: fp16 mma.sync GEMM + smooth_step + TREE ROUTING fused.
// C[128 x 128] = x_tile * W_tile^T covers trees {2bn, 2bn+1} completely, so
// the routing for those 2 trees runs in the epilogue and writes fp16 mu.
// ===========================================================================
#define A_ST 72
#define A_BYTES (128 * A_ST * 2)
#define STAGE_BYTES (2 * A_BYTES)
#define K1_STAGES 3
#define NCHUNK 16
#define CS_BYTES (128 * 132 * 4)                 // 67584: fp32 s staging
#define MU_ST 136                                 // halves per mu_stage row
#define K1_SMEM (K1_STAGES * STAGE_BYTES)         // 110592 (>= CS+MU = 102400)

__global__ __launch_bounds__(256, 2) void k1_tc() {
    extern __shared__ char smraw[];
    const uint32_t smb = smem_u32(smraw);

    const int tid  = threadIdx.x;
    const int lane = tid & 31;
    const int wid  = tid >> 5;
    const int bn   = blockIdx.x;          // fastest: 4 bn CTAs share A rows
    const int bm   = blockIdx.y;
    const int wm   = (wid & 1) * 64;
    const int wn   = (wid >> 1) * 32;

    auto load_stage = [&](int c) {
        const int slot = c % K1_STAGES;
        const uint32_t sa = smb + slot * STAGE_BYTES;
        const uint32_t sb = sa + A_BYTES;
        const __half* abase = g_xh + (size_t)bm * 128 * DDIM + c * 64;
        const __half* bbase = g_Bt + (size_t)bn * 128 * DDIM + c * 64;
        #pragma unroll
        for (int i = 0; i < 4; i++) {
            int u = tid + 256 * i;
            int row = u >> 3, seg = u & 7;
            cp16(sa + (uint32_t)(row * A_ST + seg * 8) * 2,
                 abase + (size_t)row * DDIM + seg * 8);
        }
        #pragma unroll
        for (int i = 0; i < 4; i++) {
            int u = tid + 256 * i;
            int row = u >> 3, seg = u & 7;
            cp16(sb + (uint32_t)(row * A_ST + seg * 8) * 2,
                 bbase + (size_t)row * DDIM + seg * 8);
        }
        CP_COMMIT();
    };

    float acc[4][4][4];
    #pragma unroll
    for (int t = 0; t < 4; t++)
        #pragma unroll
        for (int g = 0; g < 4; g++)
            #pragma unroll
            for (int e = 0; e < 4; e++) acc[t][g][e] = 0.0f;

    load_stage(0);
    load_stage(1);

    const int a_m   = (lane & 15);
    const int a_k8  = (lane >> 4) * 8;
    const int b_n   = ((lane >> 4) << 3) + (lane & 7);
    const int b_k8  = ((lane >> 3) & 1) * 8;

    for (int c = 0; c < NCHUNK; ++c) {
        if (c == NCHUNK - 1) { CP_WAIT(0); } else { CP_WAIT(1); }
        __syncthreads();
        if (c + 2 < NCHUNK) load_stage(c + 2);

        const int slot = c % K1_STAGES;
        const uint32_t sa = smb + slot * STAGE_BYTES;
        const uint32_t sb = sa + A_BYTES;

        #pragma unroll
        for (int kk = 0; kk < 4; kk++) {
            uint32_t af[4][4];
            #pragma unroll
            for (int t = 0; t < 4; t++) {
                int m = wm + t * 16 + a_m;
                ldsm4(af[t][0], af[t][1], af[t][2], af[t][3],
                      sa + (uint32_t)(m * A_ST + kk * 16 + a_k8) * 2);
            }
            uint32_t bf[2][4];
            #pragma unroll
            for (int g16 = 0; g16 < 2; g16++) {
                int n = wn + g16 * 16 + b_n;
                ldsm4(bf[g16][0], bf[g16][1], bf[g16][2], bf[g16][3],
                      sb + (uint32_t)(n * A_ST + kk * 16 + b_k8) * 2);
            }
            #pragma unroll
            for (int t = 0; t < 4; t++)
                #pragma unroll
                for (int g = 0; g < 4; g++)
                    mma16816h(acc[t][g], af[t], &bf[g >> 1][(g & 1) * 2]);
        }
    }
    __syncthreads();

    // ---- stage smooth_step(s) in fp32 smem [128][132] ----
    float* cs = (float*)smraw;
    const int r0 = lane >> 2;
    const int c0 = (lane & 3) * 2;
    #pragma unroll
    for (int t = 0; t < 4; t++) {
        #pragma unroll
        for (int g = 0; g < 4; g++) {
            int m = wm + t * 16 + r0;
            int n = wn + g * 8 + c0;
            cs[m * 132 + n]           = smooth_step(acc[t][g][0]);
            cs[m * 132 + n + 1]       = smooth_step(acc[t][g][1]);
            cs[(m + 8) * 132 + n]     = smooth_step(acc[t][g][2]);
            cs[(m + 8) * 132 + n + 1] = smooth_step(acc[t][g][3]);
        }
    }
    __syncthreads();

    // ---- tree routing: thread = (row, tree_half).  trees 2bn+th complete ----
    {
        __half* mu_stage = (__half*)(smraw + CS_BYTES);   // [128][MU_ST] halves
        const int r  = tid & 127;
        const int th = tid >> 7;                          // 0 or 1
        const float* srow = cs + r * 132 + th * 64;       // s for this tree

        float m[64];
        m[0] = 1.0f;
        int start = 0;
        #pragma unroll
        for (int lvl = 0; lvl < 6; ++lvl) {
            const int w = 1 << lvl;
            #pragma unroll
            for (int j = w - 1; j >= 0; --j) {
                float sv = srow[start + j];
                float p  = m[j];
                m[2 * j]     = p * sv;
                m[2 * j + 1] = p * (1.0f - sv);
            }
            start += w;
        }
        #pragma unroll
        for (int g = 0; g < 8; ++g) {
            __half hb[8];
            #pragma unroll
            for (int i = 0; i < 8; ++i)
                hb[i] = __float2half(m[g * 8 + i]);
            *(uint4*)&mu_stage[r * MU_ST + th * 64 + g * 8] = *(uint4*)hb;
        }
    }
    __syncthreads();

    // ---- coalesced mu store: per row 128 halves = 256B contiguous ----
    {
        __half* mu_stage = (__half*)(smraw + CS_BYTES);
        const int row  = tid >> 1;
        const int half = tid & 1;
        const uint4* src = (const uint4*)&mu_stage[row * MU_ST + half * 64];
        uint4* dst = (uint4*)(g_mu + ((size_t)bm * 128 + row) * NPAD
                              + bn * 128 + half * 64);
        #pragma unroll
        for (int j = 0; j < 8; j++) dst[j] = src[j];
    }
}

// ===========================================================================
// K3: leaf GEMM on tensor cores (fp16 single-pass).
// out[B x 128] = mu[B x 512] * LW[128 x 512]^T
// ===========================================================================
#define NCHUNK3 8

__global__ __launch_bounds__(256, 2) void k3_leaf(float* __restrict__ out) {
    extern __shared__ char smraw[];
    const uint32_t smb = smem_u32(smraw);

    const int tid  = threadIdx.x;
    const int lane = tid & 31;
    const int wid  = tid >> 5;
    const int bm   = blockIdx.x;
    const int wm   = (wid & 1) * 64;
    const int wn   = (wid >> 1) * 32;

    auto load_stage = [&](int c) {
        const int slot = c % K1_STAGES;
        const uint32_t sa = smb + slot * STAGE_BYTES;
        const uint32_t sb = sa + A_BYTES;
        const __half* abase = g_mu + (size_t)bm * 128 * NPAD + c * 64;
        const __half* bbase = g_LBh + c * 64;
        #pragma unroll
        for (int i = 0; i < 4; i++) {
            int u = tid + 256 * i;
            int row = u >> 3, seg = u & 7;
            cp16(sa + (uint32_t)(row * A_ST + seg * 8) * 2,
                 abase + (size_t)row * NPAD + seg * 8);
        }
        #pragma unroll
        for (int i = 0; i < 4; i++) {
            int u = tid + 256 * i;
            int row = u >> 3, seg = u & 7;
            cp16(sb + (uint32_t)(row * A_ST + seg * 8) * 2,
                 bbase + (size_t)row * NPAD + seg * 8);
        }
        CP_COMMIT();
    };

    float acc[4][4][4];
    #pragma unroll
    for (int t = 0; t < 4; t++)
        #pragma unroll
        for (int g = 0; g < 4; g++)
            #pragma unroll
            for (int e = 0; e < 4; e++) acc[t][g][e] = 0.0f;

    load_stage(0);
    load_stage(1);

    const int a_m   = (lane & 15);
    const int a_k8  = (lane >> 4) * 8;
    const int b_n   = ((lane >> 4) << 3) + (lane & 7);
    const int b_k8  = ((lane >> 3) & 1) * 8;

    for (int c = 0; c < NCHUNK3; ++c) {
        if (c == NCHUNK3 - 1) { CP_WAIT(0); } else { CP_WAIT(1); }
        __syncthreads();
        if (c + 2 < NCHUNK3) load_stage(c + 2);

        const int slot = c % K1_STAGES;
        const uint32_t sa = smb + slot * STAGE_BYTES;
        const uint32_t sb = sa + A_BYTES;

        #pragma unroll
        for (int kk = 0; kk < 4; kk++) {
            uint32_t af[4][4];
            #pragma unroll
            for (int t = 0; t < 4; t++) {
                int m = wm + t * 16 + a_m;
                ldsm4(af[t][0], af[t][1], af[t][2], af[t][3],
                      sa + (uint32_t)(m * A_ST + kk * 16 + a_k8) * 2);
            }
            uint32_t bf[2][4];
            #pragma unroll
            for (int g16 = 0; g16 < 2; g16++) {
                int n = wn + g16 * 16 + b_n;
                ldsm4(bf[g16][0], bf[g16][1], bf[g16][2], bf[g16][3],
                      sb + (uint32_t)(n * A_ST + kk * 16 + b_k8) * 2);
            }
            #pragma unroll
            for (int t = 0; t < 4; t++)
                #pragma unroll
                for (int g = 0; g < 4; g++)
                    mma16816h(acc[t][g], af[t], &bf[g >> 1][(g & 1) * 2]);
        }
    }
    __syncthreads();

    float* cs = (float*)smraw;          // [128][132]
    const int r0 = lane >> 2;
    const int c0 = (lane & 3) * 2;
    #pragma unroll
    for (int t = 0; t < 4; t++) {
        #pragma unroll
        for (int g = 0; g < 4; g++) {
            int m = wm + t * 16 + r0;
            int n = wn + g * 8 + c0;
            cs[m * 132 + n]           = acc[t][g][0];
            cs[m * 132 + n + 1]       = acc[t][g][1];
            cs[(m + 8) * 132 + n]     = acc[t][g][2];
            cs[(m + 8) * 132 + n + 1] = acc[t][g][3];
        }
    }
    __syncthreads();

    {
        const int row  = tid >> 1;
        const int half = tid & 1;
        float4* dst = (float4*)(out + ((size_t)bm * 128 + row) * ODIM + half * 64);
        const float* srcr = cs + row * 132 + half * 64;
        #pragma unroll
        for (int j = 0; j < 16; j++)
            dst[j] = *(const float4*)(srcr + j * 4);
    }
}

// ===========================================================================
// Launch
// ===========================================================================
extern "C" void kernel_launch(void* const* d_in, const int* in_sizes, int n_in,
                              void* d_out, int out_size) {
    const float* x  = (const float*)d_in[0];   // [B, 1024]
    const float* nw = (const float*)d_in[1];   // [8, 1024, 63]
    const float* lw = (const float*)d_in[2];   // [8, 128, 64]
    float* out = (float*)d_out;                // [B, 128]

    int Brows = in_sizes[0] / DDIM;            // 32768

    cudaFuncSetAttribute(k1_tc,   cudaFuncAttributeMaxDynamicSharedMemorySize, K1_SMEM);
    cudaFuncSetAttribute(k3_leaf, cudaFuncAttributeMaxDynamicSharedMemorySize, K1_SMEM);

    convert_x<<< (Brows * DDIM / 4 + 255) / 256, 256 >>>(x);
    repack_b <<< (NPAD * DDIM + 255) / 256, 256 >>>(nw);
    repack_lb<<< (ODIM * NPAD + 255) / 256, 256 >>>(lw);
    k1_tc    <<< dim3(NPAD / 128, Brows / 128), 256, K1_SMEM >>>();
    k3_leaf  <<< Brows / 128, 256, K1_SMEM >>>(out);
}

// round 10
// speedup vs baseline: 4.8707x; 1.0020x over previous
#include <cuda_runtime.h>
#include <cuda_bf16.h>
#include <cuda_fp16.h>
#include <cstdint>

// Problem constants
#define BMAXR 32768
#define DDIM  1024
#define TTREE 8
#define NODES 63
#define LEAVES 64
#define NPAD  512
#define ODIM  128

// Scratch (static device globals -- no runtime allocation)
__device__ __align__(256) __half  g_xh[(size_t)BMAXR * DDIM];     // fp16 x
__device__ __align__(256) __half  g_Bt[(size_t)NPAD * DDIM];      // fp16 W [n][k]
__device__ __align__(256) __half  g_mu[(size_t)BMAXR * NPAD];     // fp16 mu
__device__ __align__(256) __half  g_LBh[(size_t)ODIM * NPAD];     // fp16 LW [o][k]

// ===========================================================================
// PTX helpers (all arch-generic: sm_80+ / sm_75+)
// ===========================================================================
__device__ __forceinline__ uint32_t smem_u32(const void* p) {
    uint32_t a;
    asm("{ .reg .u64 t; cvta.to.shared.u64 t, %1; cvt.u32.u64 %0, t; }"
        : "=r"(a) : "l"(p));
    return a;
}
__device__ __forceinline__ void cp16(uint32_t dst, const void* src) {
    asm volatile("cp.async.cg.shared.global [%0], [%1], 16;"
                 :: "r"(dst), "l"(src) : "memory");
}
#define CP_COMMIT() asm volatile("cp.async.commit_group;" ::: "memory")
#define CP_WAIT(n)  asm volatile("cp.async.wait_group %0;" :: "n"(n) : "memory")

__device__ __forceinline__ void ldsm4(uint32_t& r0, uint32_t& r1,
                                      uint32_t& r2, uint32_t& r3, uint32_t addr) {
    asm volatile("ldmatrix.sync.aligned.m8n8.x4.shared.b16 {%0,%1,%2,%3}, [%4];"
                 : "=r"(r0), "=r"(r1), "=r"(r2), "=r"(r3) : "r"(addr));
}
// fp16 mma
__device__ __forceinline__ void mma16816h(float* d, const uint32_t* a,
                                          const uint32_t* b) {
    asm volatile("mma.sync.aligned.m16n8k16.row.col.f32.f16.f16.f32 "
                 "{%0,%1,%2,%3},{%4,%5,%6,%7},{%8,%9},{%0,%1,%2,%3};"
                 : "+f"(d[0]), "+f"(d[1]), "+f"(d[2]), "+f"(d[3])
                 : "r"(a[0]), "r"(a[1]), "r"(a[2]), "r"(a[3]),
                   "r"(b[0]), "r"(b[1]));
}

__device__ __forceinline__ float smooth_step(float u) {
    if (u <= -0.5f) return 0.0f;
    if (u >= 0.5f)  return 1.0f;
    return -2.0f * u * u * u + 1.5f * u + 0.5f;
}

// ===========================================================================
// Pre-pass kernels
// ===========================================================================
__global__ void convert_x(const float* __restrict__ x) {
    int i = blockIdx.x * blockDim.x + threadIdx.x;     // over n/4 float4
    float4 v = ((const float4*)x)[i];
    __half h[4];
    h[0] = __float2half(v.x); h[1] = __float2half(v.y);
    h[2] = __float2half(v.z); h[3] = __float2half(v.w);
    *(uint64_t*)&g_xh[(size_t)i * 4] = *(uint64_t*)h;
}

__global__ void repack_b(const float* __restrict__ nw) {
    int idx = blockIdx.x * blockDim.x + threadIdx.x;   // over NPAD*DDIM
    if (idx >= NPAD * DDIM) return;
    int n = idx / DDIM, k = idx % DDIM;
    int t = n >> 6, i = n & 63;
    float w = 0.0f;
    if (i < NODES) w = nw[((size_t)t * DDIM + k) * NODES + i];
    g_Bt[idx] = __float2half(w);
}

// leaf weights -> [o][k] fp16, k = t*64 + l
__global__ void repack_lb(const float* __restrict__ lw) {
    int idx = blockIdx.x * blockDim.x + threadIdx.x;   // over ODIM*NPAD
    if (idx >= ODIM * NPAD) return;
    int o = idx / NPAD, k = idx % NPAD;
    int t = k >> 6, l = k & 63;
    g_LBh[idx] = __float2half(lw[((size_t)t * ODIM + o) * LEAVES + l]);
}

// ===========================================================================
// K1: fp16 mma.sync GEMM + smooth_step + TREE ROUTING fused.
// C[128 x 128] = x_tile * W_tile^T covers trees {2bn, 2bn+1} completely, so
// the routing for those 2 trees runs in the epilogue and writes fp16 mu.
// cs stride = 133 (odd word-stride, gcd(5,32)=1): conflict-free scalar
// staging stores AND routing loads (133%32=5 -> 32 distinct banks/warp).
// ===========================================================================
#define A_ST 72
#define A_BYTES (128 * A_ST * 2)
#define STAGE_BYTES (2 * A_BYTES)
#define K1_STAGES 3
#define NCHUNK 16
#define CS_ST 133                                 // fp32 words per cs row
#define CS_BYTES (128 * CS_ST * 4)                // 68096
#define MU_ST 136                                 // halves per mu_stage row
#define K1_SMEM (K1_STAGES * STAGE_BYTES)         // 110592 (>= CS+MU = 102912)

__global__ __launch_bounds__(256, 2) void k1_tc() {
    extern __shared__ char smraw[];
    const uint32_t smb = smem_u32(smraw);

    const int tid  = threadIdx.x;
    const int lane = tid & 31;
    const int wid  = tid >> 5;
    const int bn   = blockIdx.x;          // fastest: 4 bn CTAs share A rows
    const int bm   = blockIdx.y;
    const int wm   = (wid & 1) * 64;
    const int wn   = (wid >> 1) * 32;

    auto load_stage = [&](int c) {
        const int slot = c % K1_STAGES;
        const uint32_t sa = smb + slot * STAGE_BYTES;
        const uint32_t sb = sa + A_BYTES;
        const __half* abase = g_xh + (size_t)bm * 128 * DDIM + c * 64;
        const __half* bbase = g_Bt + (size_t)bn * 128 * DDIM + c * 64;
        #pragma unroll
        for (int i = 0; i < 4; i++) {
            int u = tid + 256 * i;
            int row = u >> 3, seg = u & 7;
            cp16(sa + (uint32_t)(row * A_ST + seg * 8) * 2,
                 abase + (size_t)row * DDIM + seg * 8);
        }
        #pragma unroll
        for (int i = 0; i < 4; i++) {
            int u = tid + 256 * i;
            int row = u >> 3, seg = u & 7;
            cp16(sb + (uint32_t)(row * A_ST + seg * 8) * 2,
                 bbase + (size_t)row * DDIM + seg * 8);
        }
        CP_COMMIT();
    };

    float acc[4][4][4];
    #pragma unroll
    for (int t = 0; t < 4; t++)
        #pragma unroll
        for (int g = 0; g < 4; g++)
            #pragma unroll
            for (int e = 0; e < 4; e++) acc[t][g][e] = 0.0f;

    load_stage(0);
    load_stage(1);

    const int a_m   = (lane & 15);
    const int a_k8  = (lane >> 4) * 8;
    const int b_n   = ((lane >> 4) << 3) + (lane & 7);
    const int b_k8  = ((lane >> 3) & 1) * 8;

    for (int c = 0; c < NCHUNK; ++c) {
        if (c == NCHUNK - 1) { CP_WAIT(0); } else { CP_WAIT(1); }
        __syncthreads();
        if (c + 2 < NCHUNK) load_stage(c + 2);

        const int slot = c % K1_STAGES;
        const uint32_t sa = smb + slot * STAGE_BYTES;
        const uint32_t sb = sa + A_BYTES;

        #pragma unroll
        for (int kk = 0; kk < 4; kk++) {
            uint32_t af[4][4];
            #pragma unroll
            for (int t = 0; t < 4; t++) {
                int m = wm + t * 16 + a_m;
                ldsm4(af[t][0], af[t][1], af[t][2], af[t][3],
                      sa + (uint32_t)(m * A_ST + kk * 16 + a_k8) * 2);
            }
            uint32_t bf[2][4];
            #pragma unroll
            for (int g16 = 0; g16 < 2; g16++) {
                int n = wn + g16 * 16 + b_n;
                ldsm4(bf[g16][0], bf[g16][1], bf[g16][2], bf[g16][3],
                      sb + (uint32_t)(n * A_ST + kk * 16 + b_k8) * 2);
            }
            #pragma unroll
            for (int t = 0; t < 4; t++)
                #pragma unroll
                for (int g = 0; g < 4; g++)
                    mma16816h(acc[t][g], af[t], &bf[g >> 1][(g & 1) * 2]);
        }
    }
    __syncthreads();

    // ---- stage smooth_step(s) in fp32 smem [128][CS_ST] (scalar stores) ----
    float* cs = (float*)smraw;
    const int r0 = lane >> 2;
    const int c0 = (lane & 3) * 2;
    #pragma unroll
    for (int t = 0; t < 4; t++) {
        #pragma unroll
        for (int g = 0; g < 4; g++) {
            int m = wm + t * 16 + r0;
            int n = wn + g * 8 + c0;
            cs[m * CS_ST + n]           = smooth_step(acc[t][g][0]);
            cs[m * CS_ST + n + 1]       = smooth_step(acc[t][g][1]);
            cs[(m + 8) * CS_ST + n]     = smooth_step(acc[t][g][2]);
            cs[(m + 8) * CS_ST + n + 1] = smooth_step(acc[t][g][3]);
        }
    }
    __syncthreads();

    // ---- tree routing: thread = (row, tree_half).  trees 2bn+th complete ----
    {
        __half* mu_stage = (__half*)(smraw + CS_BYTES);   // [128][MU_ST] halves
        const int r  = tid & 127;
        const int th = tid >> 7;                          // 0 or 1
        const float* srow = cs + r * CS_ST + th * 64;     // s for this tree

        float m[64];
        m[0] = 1.0f;
        int start = 0;
        #pragma unroll
        for (int lvl = 0; lvl < 6; ++lvl) {
            const int w = 1 << lvl;
            #pragma unroll
            for (int j = w - 1; j >= 0; --j) {
                float sv = srow[start + j];
                float p  = m[j];
                m[2 * j]     = p * sv;
                m[2 * j + 1] = p * (1.0f - sv);
            }
            start += w;
        }
        #pragma unroll
        for (int g = 0; g < 8; ++g) {
            __half hb[8];
            #pragma unroll
            for (int i = 0; i < 8; ++i)
                hb[i] = __float2half(m[g * 8 + i]);
            *(uint4*)&mu_stage[r * MU_ST + th * 64 + g * 8] = *(uint4*)hb;
        }
    }
    __syncthreads();

    // ---- coalesced mu store: per row 128 halves = 256B contiguous ----
    {
        __half* mu_stage = (__half*)(smraw + CS_BYTES);
        const int row  = tid >> 1;
        const int half = tid & 1;
        const uint4* src = (const uint4*)&mu_stage[row * MU_ST + half * 64];
        uint4* dst = (uint4*)(g_mu + ((size_t)bm * 128 + row) * NPAD
                              + bn * 128 + half * 64);
        #pragma unroll
        for (int j = 0; j < 8; j++) dst[j] = src[j];
    }
}

// ===========================================================================
// K3: leaf GEMM on tensor cores (fp16 single-pass).
// out[B x 128] = mu[B x 512] * LW[128 x 512]^T
// ===========================================================================
#define NCHUNK3 8

__global__ __launch_bounds__(256, 2) void k3_leaf(float* __restrict__ out) {
    extern __shared__ char smraw[];
    const uint32_t smb = smem_u32(smraw);

    const int tid  = threadIdx.x;
    const int lane = tid & 31;
    const int wid  = tid >> 5;
    const int bm   = blockIdx.x;
    const int wm   = (wid & 1) * 64;
    const int wn   = (wid >> 1) * 32;

    auto load_stage = [&](int c) {
        const int slot = c % K1_STAGES;
        const uint32_t sa = smb + slot * STAGE_BYTES;
        const uint32_t sb = sa + A_BYTES;
        const __half* abase = g_mu + (size_t)bm * 128 * NPAD + c * 64;
        const __half* bbase = g_LBh + c * 64;
        #pragma unroll
        for (int i = 0; i < 4; i++) {
            int u = tid + 256 * i;
            int row = u >> 3, seg = u & 7;
            cp16(sa + (uint32_t)(row * A_ST + seg * 8) * 2,
                 abase + (size_t)row * NPAD + seg * 8);
        }
        #pragma unroll
        for (int i = 0; i < 4; i++) {
            int u = tid + 256 * i;
            int row = u >> 3, seg = u & 7;
            cp16(sb + (uint32_t)(row * A_ST + seg * 8) * 2,
                 bbase + (size_t)row * NPAD + seg * 8);
        }
        CP_COMMIT();
    };

    float acc[4][4][4];
    #pragma unroll
    for (int t = 0; t < 4; t++)
        #pragma unroll
        for (int g = 0; g < 4; g++)
            #pragma unroll
            for (int e = 0; e < 4; e++) acc[t][g][e] = 0.0f;

    load_stage(0);
    load_stage(1);

    const int a_m   = (lane & 15);
    const int a_k8  = (lane >> 4) * 8;
    const int b_n   = ((lane >> 4) << 3) + (lane & 7);
    const int b_k8  = ((lane >> 3) & 1) * 8;

    for (int c = 0; c < NCHUNK3; ++c) {
        if (c == NCHUNK3 - 1) { CP_WAIT(0); } else { CP_WAIT(1); }
        __syncthreads();
        if (c + 2 < NCHUNK3) load_stage(c + 2);

        const int slot = c % K1_STAGES;
        const uint32_t sa = smb + slot * STAGE_BYTES;
        const uint32_t sb = sa + A_BYTES;

        #pragma unroll
        for (int kk = 0; kk < 4; kk++) {
            uint32_t af[4][4];
            #pragma unroll
            for (int t = 0; t < 4; t++) {
                int m = wm + t * 16 + a_m;
                ldsm4(af[t][0], af[t][1], af[t][2], af[t][3],
                      sa + (uint32_t)(m * A_ST + kk * 16 + a_k8) * 2);
            }
            uint32_t bf[2][4];
            #pragma unroll
            for (int g16 = 0; g16 < 2; g16++) {
                int n = wn + g16 * 16 + b_n;
                ldsm4(bf[g16][0], bf[g16][1], bf[g16][2], bf[g16][3],
                      sb + (uint32_t)(n * A_ST + kk * 16 + b_k8) * 2);
            }
            #pragma unroll
            for (int t = 0; t < 4; t++)
                #pragma unroll
                for (int g = 0; g < 4; g++)
                    mma16816h(acc[t][g], af[t], &bf[g >> 1][(g & 1) * 2]);
        }
    }
    __syncthreads();

    float* cs = (float*)smraw;          // [128][132]
    const int r0 = lane >> 2;
    const int c0 = (lane & 3) * 2;
    #pragma unroll
    for (int t = 0; t < 4; t++) {
        #pragma unroll
        for (int g = 0; g < 4; g++) {
            int m = wm + t * 16 + r0;
            int n = wn + g * 8 + c0;
            cs[m * 132 + n]           = acc[t][g][0];
            cs[m * 132 + n + 1]       = acc[t][g][1];
            cs[(m + 8) * 132 + n]     = acc[t][g][2];
            cs[(m + 8) * 132 + n + 1] = acc[t][g][3];
        }
    }
    __syncthreads();

    {
        const int row  = tid >> 1;
        const int half = tid & 1;
        float4* dst = (float4*)(out + ((size_t)bm * 128 + row) * ODIM + half * 64);
        const float* srcr = cs + row * 132 + half * 64;
        #pragma unroll
        for (int j = 0; j < 16; j++)
            dst[j] = *(const float4*)(srcr + j * 4);
    }
}

// ===========================================================================
// Launch
// ===========================================================================
extern "C" void kernel_launch(void* const* d_in, const int* in_sizes, int n_in,
                              void* d_out, int out_size) {
    const float* x  = (const float*)d_in[0];   // [B, 1024]
    const float* nw = (const float*)d_in[1];   // [8, 1024, 63]
    const float* lw = (const float*)d_in[2];   // [8, 128, 64]
    float* out = (float*)d_out;                // [B, 128]

    int Brows = in_sizes[0] / DDIM;            // 32768

    cudaFuncSetAttribute(k1_tc,   cudaFuncAttributeMaxDynamicSharedMemorySize, K1_SMEM);
    cudaFuncSetAttribute(k3_leaf, cudaFuncAttributeMaxDynamicSharedMemorySize, K1_SMEM);

    convert_x<<< (Brows * DDIM / 4 + 255) / 256, 256 >>>(x);
    repack_b <<< (NPAD * DDIM + 255) / 256, 256 >>>(nw);
    repack_lb<<< (ODIM * NPAD + 255) / 256, 256 >>>(lw);
    k1_tc    <<< dim3(NPAD / 128, Brows / 128), 256, K1_SMEM >>>();
    k3_leaf  <<< Brows / 128, 256, K1_SMEM >>>(out);
}

// round 11
// speedup vs baseline: 5.6255x; 1.1550x over previous
#include <cuda_runtime.h>
#include <cuda_bf16.h>
#include <cuda_fp16.h>
#include <cstdint>

// Problem constants
#define BMAXR 32768
#define DDIM  1024
#define TTREE 8
#define NODES 63
#define LEAVES 64
#define NPAD  512
#define ODIM  128

// Scratch (static device globals -- no runtime allocation)
__device__ __align__(256) __half  g_xh[(size_t)BMAXR * DDIM];     // fp16 x
__device__ __align__(256) __half  g_Bt[(size_t)NPAD * DDIM];      // fp16 W [n][k]
__device__ __align__(256) __half  g_mu[(size_t)BMAXR * NPAD];     // fp16 mu
__device__ __align__(256) __half  g_LBh[(size_t)ODIM * NPAD];     // fp16 LW [o][k]

// ===========================================================================
// PTX helpers (all arch-generic: sm_80+ / sm_75+)
// ===========================================================================
__device__ __forceinline__ uint32_t smem_u32(const void* p) {
    uint32_t a;
    asm("{ .reg .u64 t; cvta.to.shared.u64 t, %1; cvt.u32.u64 %0, t; }"
        : "=r"(a) : "l"(p));
    return a;
}
__device__ __forceinline__ void cp16(uint32_t dst, const void* src) {
    asm volatile("cp.async.cg.shared.global [%0], [%1], 16;"
                 :: "r"(dst), "l"(src) : "memory");
}
#define CP_COMMIT() asm volatile("cp.async.commit_group;" ::: "memory")
#define CP_WAIT(n)  asm volatile("cp.async.wait_group %0;" :: "n"(n) : "memory")

__device__ __forceinline__ void ldsm4(uint32_t& r0, uint32_t& r1,
                                      uint32_t& r2, uint32_t& r3, uint32_t addr) {
    asm volatile("ldmatrix.sync.aligned.m8n8.x4.shared.b16 {%0,%1,%2,%3}, [%4];"
                 : "=r"(r0), "=r"(r1), "=r"(r2), "=r"(r3) : "r"(addr));
}
// fp16 mma
__device__ __forceinline__ void mma16816h(float* d, const uint32_t* a,
                                          const uint32_t* b) {
    asm volatile("mma.sync.aligned.m16n8k16.row.col.f32.f16.f16.f32 "
                 "{%0,%1,%2,%3},{%4,%5,%6,%7},{%8,%9},{%0,%1,%2,%3};"
                 : "+f"(d[0]), "+f"(d[1]), "+f"(d[2]), "+f"(d[3])
                 : "r"(a[0]), "r"(a[1]), "r"(a[2]), "r"(a[3]),
                   "r"(b[0]), "r"(b[1]));
}

__device__ __forceinline__ float smooth_step(float u) {
    if (u <= -0.5f) return 0.0f;
    if (u >= 0.5f)  return 1.0f;
    return -2.0f * u * u * u + 1.5f * u + 0.5f;
}

// ===========================================================================
// Pre-pass kernels
// ===========================================================================
__global__ void convert_x(const float* __restrict__ x) {
    int i = blockIdx.x * blockDim.x + threadIdx.x;     // over n/4 float4
    float4 v = ((const float4*)x)[i];
    __half h[4];
    h[0] = __float2half(v.x); h[1] = __float2half(v.y);
    h[2] = __float2half(v.z); h[3] = __float2half(v.w);
    *(uint64_t*)&g_xh[(size_t)i * 4] = *(uint64_t*)h;
}

__global__ void repack_b(const float* __restrict__ nw) {
    int idx = blockIdx.x * blockDim.x + threadIdx.x;   // over NPAD*DDIM
    if (idx >= NPAD * DDIM) return;
    int n = idx / DDIM, k = idx % DDIM;
    int t = n >> 6, i = n & 63;
    float w = 0.0f;
    if (i < NODES) w = nw[((size_t)t * DDIM + k) * NODES + i];
    g_Bt[idx] = __float2half(w);
}

// leaf weights -> [o][k] fp16, k = t*64 + l
__global__ void repack_lb(const float* __restrict__ lw) {
    int idx = blockIdx.x * blockDim.x + threadIdx.x;   // over ODIM*NPAD
    if (idx >= ODIM * NPAD) return;
    int o = idx / NPAD, k = idx % NPAD;
    int t = k >> 6, l = k & 63;
    g_LBh[idx] = __float2half(lw[((size_t)t * ODIM + o) * LEAVES + l]);
}

// ===========================================================================
// K1: fp16 mma.sync GEMM + smooth_step + TREE ROUTING fused.
// C[128 x 128] = x_tile * W_tile^T covers trees {2bn, 2bn+1} completely; the
// routing runs in the epilogue as a fully-unrolled depth-first path walk
// (6 live partial products, NO m[64] array -> no register spills).
// ===========================================================================
#define A_ST 72
#define A_BYTES (128 * A_ST * 2)
#define STAGE_BYTES (2 * A_BYTES)
#define K1_STAGES 3
#define NCHUNK 16
#define CS_ST 133                                 // fp32 words per cs row
#define CS_BYTES (128 * CS_ST * 4)                // 68096
#define MU_ST 136                                 // halves per mu_stage row
#define K1_SMEM (K1_STAGES * STAGE_BYTES)         // 110592 (>= CS+MU = 102912)

__global__ __launch_bounds__(256, 2) void k1_tc() {
    extern __shared__ char smraw[];
    const uint32_t smb = smem_u32(smraw);

    const int tid  = threadIdx.x;
    const int lane = tid & 31;
    const int wid  = tid >> 5;
    const int bn   = blockIdx.x;          // fastest: 4 bn CTAs share A rows
    const int bm   = blockIdx.y;
    const int wm   = (wid & 1) * 64;
    const int wn   = (wid >> 1) * 32;

    auto load_stage = [&](int c) {
        const int slot = c % K1_STAGES;
        const uint32_t sa = smb + slot * STAGE_BYTES;
        const uint32_t sb = sa + A_BYTES;
        const __half* abase = g_xh + (size_t)bm * 128 * DDIM + c * 64;
        const __half* bbase = g_Bt + (size_t)bn * 128 * DDIM + c * 64;
        #pragma unroll
        for (int i = 0; i < 4; i++) {
            int u = tid + 256 * i;
            int row = u >> 3, seg = u & 7;
            cp16(sa + (uint32_t)(row * A_ST + seg * 8) * 2,
                 abase + (size_t)row * DDIM + seg * 8);
        }
        #pragma unroll
        for (int i = 0; i < 4; i++) {
            int u = tid + 256 * i;
            int row = u >> 3, seg = u & 7;
            cp16(sb + (uint32_t)(row * A_ST + seg * 8) * 2,
                 bbase + (size_t)row * DDIM + seg * 8);
        }
        CP_COMMIT();
    };

    float acc[4][4][4];
    #pragma unroll
    for (int t = 0; t < 4; t++)
        #pragma unroll
        for (int g = 0; g < 4; g++)
            #pragma unroll
            for (int e = 0; e < 4; e++) acc[t][g][e] = 0.0f;

    load_stage(0);
    load_stage(1);

    const int a_m   = (lane & 15);
    const int a_k8  = (lane >> 4) * 8;
    const int b_n   = ((lane >> 4) << 3) + (lane & 7);
    const int b_k8  = ((lane >> 3) & 1) * 8;

    for (int c = 0; c < NCHUNK; ++c) {
        if (c == NCHUNK - 1) { CP_WAIT(0); } else { CP_WAIT(1); }
        __syncthreads();
        if (c + 2 < NCHUNK) load_stage(c + 2);

        const int slot = c % K1_STAGES;
        const uint32_t sa = smb + slot * STAGE_BYTES;
        const uint32_t sb = sa + A_BYTES;

        #pragma unroll
        for (int kk = 0; kk < 4; kk++) {
            uint32_t af[4][4];
            #pragma unroll
            for (int t = 0; t < 4; t++) {
                int m = wm + t * 16 + a_m;
                ldsm4(af[t][0], af[t][1], af[t][2], af[t][3],
                      sa + (uint32_t)(m * A_ST + kk * 16 + a_k8) * 2);
            }
            uint32_t bf[2][4];
            #pragma unroll
            for (int g16 = 0; g16 < 2; g16++) {
                int n = wn + g16 * 16 + b_n;
                ldsm4(bf[g16][0], bf[g16][1], bf[g16][2], bf[g16][3],
                      sb + (uint32_t)(n * A_ST + kk * 16 + b_k8) * 2);
            }
            #pragma unroll
            for (int t = 0; t < 4; t++)
                #pragma unroll
                for (int g = 0; g < 4; g++)
                    mma16816h(acc[t][g], af[t], &bf[g >> 1][(g & 1) * 2]);
        }
    }
    __syncthreads();

    // ---- stage smooth_step(s) in fp32 smem [128][CS_ST] ----
    float* cs = (float*)smraw;
    const int r0 = lane >> 2;
    const int c0 = (lane & 3) * 2;
    #pragma unroll
    for (int t = 0; t < 4; t++) {
        #pragma unroll
        for (int g = 0; g < 4; g++) {
            int m = wm + t * 16 + r0;
            int n = wn + g * 8 + c0;
            cs[m * CS_ST + n]           = smooth_step(acc[t][g][0]);
            cs[m * CS_ST + n + 1]       = smooth_step(acc[t][g][1]);
            cs[(m + 8) * CS_ST + n]     = smooth_step(acc[t][g][2]);
            cs[(m + 8) * CS_ST + n + 1] = smooth_step(acc[t][g][3]);
        }
    }
    __syncthreads();

    // ---- tree routing: depth-first walk, 6 live partials, no spills ----
    // thread = (row r, tree_half th); trees 2bn+th are complete in this tile.
    // Leaf l = i0*32+i1*16+i2*8+i3*4+i4*2+i5 (bit 0 -> s, bit 1 -> 1-s),
    // identical multiplication tree to the BFS version (bit-identical).
    {
        __half* mu_stage = (__half*)(smraw + CS_BYTES);   // [128][MU_ST] halves
        const int r  = tid & 127;
        const int th = tid >> 7;                          // 0 or 1
        const float* srow = cs + r * CS_ST + th * 64;
        __half* mrow = &mu_stage[r * MU_ST + th * 64];

        const float s0 = srow[0];
        #pragma unroll
        for (int i0 = 0; i0 < 2; i0++) {
            const float p1 = i0 ? (1.0f - s0) : s0;
            const float s1 = srow[1 + i0];
            #pragma unroll
            for (int i1 = 0; i1 < 2; i1++) {
                const float p2 = p1 * (i1 ? (1.0f - s1) : s1);
                const float s2 = srow[3 + i0 * 2 + i1];
                #pragma unroll
                for (int i2 = 0; i2 < 2; i2++) {
                    const float p3 = p2 * (i2 ? (1.0f - s2) : s2);
                    const float s3 = srow[7 + i0 * 4 + i1 * 2 + i2];
                    __half hb[8];
                    #pragma unroll
                    for (int i3 = 0; i3 < 2; i3++) {
                        const float p4 = p3 * (i3 ? (1.0f - s3) : s3);
                        const float s4 = srow[15 + i0 * 8 + i1 * 4 + i2 * 2 + i3];
                        #pragma unroll
                        for (int i4 = 0; i4 < 2; i4++) {
                            const float p5 = p4 * (i4 ? (1.0f - s4) : s4);
                            const float s5 = srow[31 + i0 * 16 + i1 * 8 + i2 * 4
                                                  + i3 * 2 + i4];
                            #pragma unroll
                            for (int i5 = 0; i5 < 2; i5++) {
                                const float p6 = p5 * (i5 ? (1.0f - s5) : s5);
                                hb[i3 * 4 + i4 * 2 + i5] = __float2half(p6);
                            }
                        }
                    }
                    *(uint4*)&mrow[(i0 * 4 + i1 * 2 + i2) * 8] = *(uint4*)hb;
                }
            }
        }
    }
    __syncthreads();

    // ---- coalesced mu store: per row 128 halves = 256B contiguous ----
    {
        __half* mu_stage = (__half*)(smraw + CS_BYTES);
        const int row  = tid >> 1;
        const int half = tid & 1;
        const uint4* src = (const uint4*)&mu_stage[row * MU_ST + half * 64];
        uint4* dst = (uint4*)(g_mu + ((size_t)bm * 128 + row) * NPAD
                              + bn * 128 + half * 64);
        #pragma unroll
        for (int j = 0; j < 8; j++) dst[j] = src[j];
    }
}

// ===========================================================================
// K3: leaf GEMM on tensor cores (fp16 single-pass).
// out[B x 128] = mu[B x 512] * LW[128 x 512]^T
// ===========================================================================
#define NCHUNK3 8

__global__ __launch_bounds__(256, 2) void k3_leaf(float* __restrict__ out) {
    extern __shared__ char smraw[];
    const uint32_t smb = smem_u32(smraw);

    const int tid  = threadIdx.x;
    const int lane = tid & 31;
    const int wid  = tid >> 5;
    const int bm   = blockIdx.x;
    const int wm   = (wid & 1) * 64;
    const int wn   = (wid >> 1) * 32;

    auto load_stage = [&](int c) {
        const int slot = c % K1_STAGES;
        const uint32_t sa = smb + slot * STAGE_BYTES;
        const uint32_t sb = sa + A_BYTES;
        const __half* abase = g_mu + (size_t)bm * 128 * NPAD + c * 64;
        const __half* bbase = g_LBh + c * 64;
        #pragma unroll
        for (int i = 0; i < 4; i++) {
            int u = tid + 256 * i;
            int row = u >> 3, seg = u & 7;
            cp16(sa + (uint32_t)(row * A_ST + seg * 8) * 2,
                 abase + (size_t)row * NPAD + seg * 8);
        }
        #pragma unroll
        for (int i = 0; i < 4; i++) {
            int u = tid + 256 * i;
            int row = u >> 3, seg = u & 7;
            cp16(sb + (uint32_t)(row * A_ST + seg * 8) * 2,
                 bbase + (size_t)row * NPAD + seg * 8);
        }
        CP_COMMIT();
    };

    float acc[4][4][4];
    #pragma unroll
    for (int t = 0; t < 4; t++)
        #pragma unroll
        for (int g = 0; g < 4; g++)
            #pragma unroll
            for (int e = 0; e < 4; e++) acc[t][g][e] = 0.0f;

    load_stage(0);
    load_stage(1);

    const int a_m   = (lane & 15);
    const int a_k8  = (lane >> 4) * 8;
    const int b_n   = ((lane >> 4) << 3) + (lane & 7);
    const int b_k8  = ((lane >> 3) & 1) * 8;

    for (int c = 0; c < NCHUNK3; ++c) {
        if (c == NCHUNK3 - 1) { CP_WAIT(0); } else { CP_WAIT(1); }
        __syncthreads();
        if (c + 2 < NCHUNK3) load_stage(c + 2);

        const int slot = c % K1_STAGES;
        const uint32_t sa = smb + slot * STAGE_BYTES;
        const uint32_t sb = sa + A_BYTES;

        #pragma unroll
        for (int kk = 0; kk < 4; kk++) {
            uint32_t af[4][4];
            #pragma unroll
            for (int t = 0; t < 4; t++) {
                int m = wm + t * 16 + a_m;
                ldsm4(af[t][0], af[t][1], af[t][2], af[t][3],
                      sa + (uint32_t)(m * A_ST + kk * 16 + a_k8) * 2);
            }
            uint32_t bf[2][4];
            #pragma unroll
            for (int g16 = 0; g16 < 2; g16++) {
                int n = wn + g16 * 16 + b_n;
                ldsm4(bf[g16][0], bf[g16][1], bf[g16][2], bf[g16][3],
                      sb + (uint32_t)(n * A_ST + kk * 16 + b_k8) * 2);
            }
            #pragma unroll
            for (int t = 0; t < 4; t++)
                #pragma unroll
                for (int g = 0; g < 4; g++)
                    mma16816h(acc[t][g], af[t], &bf[g >> 1][(g & 1) * 2]);
        }
    }
    __syncthreads();

    float* cs = (float*)smraw;          // [128][132]
    const int r0 = lane >> 2;
    const int c0 = (lane & 3) * 2;
    #pragma unroll
    for (int t = 0; t < 4; t++) {
        #pragma unroll
        for (int g = 0; g < 4; g++) {
            int m = wm + t * 16 + r0;
            int n = wn + g * 8 + c0;
            cs[m * 132 + n]           = acc[t][g][0];
            cs[m * 132 + n + 1]       = acc[t][g][1];
            cs[(m + 8) * 132 + n]     = acc[t][g][2];
            cs[(m + 8) * 132 + n + 1] = acc[t][g][3];
        }
    }
    __syncthreads();

    {
        const int row  = tid >> 1;
        const int half = tid & 1;
        float4* dst = (float4*)(out + ((size_t)bm * 128 + row) * ODIM + half * 64);
        const float* srcr = cs + row * 132 + half * 64;
        #pragma unroll
        for (int j = 0; j < 16; j++)
            dst[j] = *(const float4*)(srcr + j * 4);
    }
}

// ===========================================================================
// Launch
// ===========================================================================
extern "C" void kernel_launch(void* const* d_in, const int* in_sizes, int n_in,
                              void* d_out, int out_size) {
    const float* x  = (const float*)d_in[0];   // [B, 1024]
    const float* nw = (const float*)d_in[1];   // [8, 1024, 63]
    const float* lw = (const float*)d_in[2];   // [8, 128, 64]
    float* out = (float*)d_out;                // [B, 128]

    int Brows = in_sizes[0] / DDIM;            // 32768

    cudaFuncSetAttribute(k1_tc,   cudaFuncAttributeMaxDynamicSharedMemorySize, K1_SMEM);
    cudaFuncSetAttribute(k3_leaf, cudaFuncAttributeMaxDynamicSharedMemorySize, K1_SMEM);

    convert_x<<< (Brows * DDIM / 4 + 255) / 256, 256 >>>(x);
    repack_b <<< (NPAD * DDIM + 255) / 256, 256 >>>(nw);
    repack_lb<<< (ODIM * NPAD + 255) / 256, 256 >>>(lw);
    k1_tc    <<< dim3(NPAD / 128, Brows / 128), 256, K1_SMEM >>>();
    k3_leaf  <<< Brows / 128, 256, K1_SMEM >>>(out);
}